// round 14
// baseline (speedup 1.0000x reference)
#include <cuda_runtime.h>
#include <cuda_fp16.h>
#include <cstdint>

// Problem constants
#define B_  32
#define T_  64
#define V_  50257
#define E_  256
#define H_  512
#define G4_ 2048   // 4*H
#define H2_ 1024   // 2*H
#define M_  2048   // T*B
#define VPAD2_ 50432  // 197*256

// mma tiling: CTA 128x256, 512 threads (16 warps 2x8), warp tile 64x32, BK=128
#define BM_ 128
#define BN_ 256
#define ST_A_BYTES 32768          // 128*128*2
#define ST_B_BYTES 65536          // 256*128*2
#define ST_BYTES   98304
#define SMEM_DYN   (2 * ST_BYTES) // 196608
#define NTILE_ ((M_ / BM_) * (VPAD2_ / BN_))   // 3152

// ---------------- scratch (device globals; no allocation allowed) ----------------
__device__ float g_base[B_ * G4_];
__device__ float g_xg[M_ * G4_];
__device__ float g_hs[M_ * H_];
__device__ __align__(16) __half g_embp[(size_t)M_ * E_];            // gathered emb A-frags (K2)
__device__ __align__(16) __half g_wihp[(size_t)G4_ * E_];           // W_ih B-frags (K2)
__device__ __align__(16) __half g_hsp[(size_t)M_ * H_];             // hs A-frags (K4)
__device__ __align__(16) __half g_w1p[(size_t)H2_ * H_];            // W1 B-frags (K4)
__device__ __align__(16) __half g_hidp[(size_t)M_ * H2_];           // hid A-frags (K5), written by K4
__device__ __align__(16) __half g_w2p[(size_t)VPAD2_ * H2_];        // W2 B-frags (K5)

// ---------------- helpers ----------------
__device__ __forceinline__ void mma_f16(float* d, const uint32_t* a, uint32_t b0, uint32_t b1) {
    asm volatile(
        "mma.sync.aligned.m16n8k16.row.col.f32.f16.f16.f32 "
        "{%0,%1,%2,%3}, {%4,%5,%6,%7}, {%8,%9}, {%0,%1,%2,%3};\n"
        : "+f"(d[0]), "+f"(d[1]), "+f"(d[2]), "+f"(d[3])
        : "r"(a[0]), "r"(a[1]), "r"(a[2]), "r"(a[3]), "r"(b0), "r"(b1));
}

__device__ __forceinline__ float sigf(float x) {
    return __fdividef(1.f, 1.f + __expf(-x));
}
__device__ __forceinline__ float ftanh(float x) {
    float e = __expf(2.f * x);
    return 1.f - __fdividef(2.f, e + 1.f);
}

__device__ __forceinline__ uint32_t smem_u32(const void* p) {
    return (uint32_t)__cvta_generic_to_shared(p);
}

__device__ __forceinline__ void cp16(uint32_t dst, const void* src) {
    asm volatile("cp.async.cg.shared.global [%0], [%1], 16;\n"
                 :: "r"(dst), "l"(src) : "memory");
}

__device__ __forceinline__ uint32_t pack2(float lo, float hi) {
    __half2 h = __floats2half2_rn(lo, hi);
    return *(uint32_t*)&h;
}

// ---------------- K1: base gates = features @ W_hh^T + b_ih + b_hh ----------------
__global__ void base_kernel(const float* __restrict__ feat,
                            const float* __restrict__ W_hh,
                            const float* __restrict__ b_ih,
                            const float* __restrict__ b_hh,
                            float* __restrict__ base) {
    __shared__ float4 f4[H_ / 4];
    int b = blockIdx.x;
    if (threadIdx.x < H_ / 4)
        f4[threadIdx.x] = ((const float4*)(feat + (size_t)b * H_))[threadIdx.x];
    __syncthreads();
    for (int g = threadIdx.x; g < G4_; g += blockDim.x) {
        const float4* w4 = (const float4*)(W_hh + (size_t)g * H_);
        float s = 0.f;
        #pragma unroll 8
        for (int k = 0; k < H_ / 4; k++) {
            float4 w = w4[k], f = f4[k];
            s += w.x * f.x + w.y * f.y + w.z * f.z + w.w * f.w;
        }
        base[b * G4_ + g] = s + b_ih[g] + b_hh[g];
    }
}

// ---------------- K3: LSTM scan (depth-8 prefetch) ----------------
__global__ void lstm_scan(const float* __restrict__ xg,
                          const float* __restrict__ base,
                          float* __restrict__ hs) {
    int idx = blockIdx.x * blockDim.x + threadIdx.x;
    int b = idx >> 9, h = idx & 511;
    float bi = base[b * G4_ + h];
    float bff = base[b * G4_ + H_ + h];
    float bg = base[b * G4_ + 2 * H_ + h];
    float bo = base[b * G4_ + 3 * H_ + h];

    const float* xr = xg + (size_t)b * G4_ + h;
    const size_t step = (size_t)B_ * G4_;

    float4 pf[8];
    #pragma unroll
    for (int j = 0; j < 8; j++) {
        const float* p = xr + (size_t)j * step;
        pf[j] = make_float4(p[0], p[H_], p[2 * H_], p[3 * H_]);
    }

    float c = 0.f;
    float* hp = hs + (size_t)b * H_ + h;
    #pragma unroll 8
    for (int t = 0; t < T_; t++) {
        float4 cur = pf[t & 7];
        if (t + 8 < T_) {
            const float* p = xr + (size_t)(t + 8) * step;
            pf[t & 7] = make_float4(p[0], p[H_], p[2 * H_], p[3 * H_]);
        }
        float i = sigf(cur.x + bi);
        float f = sigf(cur.y + bff);
        float g = ftanh(cur.z + bg);
        float o = sigf(cur.w + bo);
        c = f * c + i * g;
        hp[(size_t)t * B_ * H_] = o * ftanh(c);
    }
}

// ---------------- generic A-perm: fp32 [M x K] -> fp16 m16n8k16 A-fragments ----------------
__global__ void permA_g(const float* __restrict__ src, uint4* __restrict__ outp,
                        int M, int K, int kcnt) {
    int ktcnt = K >> 4;
    int total = (M >> 4) * ktcnt * 32;
    for (int i = blockIdx.x * blockDim.x + threadIdx.x; i < total; i += gridDim.x * blockDim.x) {
        int lane = i & 31;
        int kt = (i >> 5) % ktcnt;
        int mt = (i >> 5) / ktcnt;
        int g = lane >> 2, q = lane & 3;
        int r0 = mt * 16 + g, r1 = r0 + 8;
        int c0 = kt * 16 + 2 * q;
        const float* p0 = src + (size_t)r0 * K + c0;
        const float* p1 = src + (size_t)r1 * K + c0;
        float2 v0 = *(const float2*)(p0);
        float2 v1 = *(const float2*)(p1);
        float2 v2 = *(const float2*)(p0 + 8);
        float2 v3 = *(const float2*)(p1 + 8);
        uint4 o;
        o.x = pack2(v0.x, v0.y);
        o.y = pack2(v1.x, v1.y);
        o.z = pack2(v2.x, v2.y);
        o.w = pack2(v3.x, v3.y);
        int mb = mt >> 3, tm = mt & 7, kc = kt >> 3, k16 = kt & 7;
        outp[((((mb * kcnt + kc) * 8 + k16) * 8 + tm) << 5) + lane] = o;
    }
}

// ---------------- gathered emb A-perm (K2): rows are emb[tok(m)] ----------------
__global__ void permA_emb(const float* __restrict__ emb, const int* __restrict__ captions,
                          uint4* __restrict__ outp) {
    const int K = E_, ktcnt = E_ / 16, kcnt = E_ / 128;   // 16, 2
    int total = (M_ / 16) * ktcnt * 32;
    for (int i = blockIdx.x * blockDim.x + threadIdx.x; i < total; i += gridDim.x * blockDim.x) {
        int lane = i & 31;
        int kt = (i >> 5) % ktcnt;
        int mt = (i >> 5) / ktcnt;
        int g = lane >> 2, q = lane & 3;
        int m0 = mt * 16 + g, m1 = m0 + 8;
        int c0 = kt * 16 + 2 * q;
        int b0 = m0 & 31, t0 = m0 >> 5;
        int b1 = m1 & 31, t1 = m1 >> 5;
        int tok0 = captions[b0 * T_ + (t0 ? t0 - 1 : 0)];
        int tok1 = captions[b1 * T_ + (t1 ? t1 - 1 : 0)];
        const float* p0 = emb + (size_t)tok0 * K + c0;
        const float* p1 = emb + (size_t)tok1 * K + c0;
        float2 v0 = *(const float2*)(p0);
        float2 v1 = *(const float2*)(p1);
        float2 v2 = *(const float2*)(p0 + 8);
        float2 v3 = *(const float2*)(p1 + 8);
        uint4 o;
        o.x = pack2(v0.x, v0.y);
        o.y = pack2(v1.x, v1.y);
        o.z = pack2(v2.x, v2.y);
        o.w = pack2(v3.x, v3.y);
        int mb = mt >> 3, tm = mt & 7, kc = kt >> 3, k16 = kt & 7;
        outp[((((mb * kcnt + kc) * 8 + k16) * 8 + tm) << 5) + lane] = o;
    }
}

// ---------------- generic B-perm: fp32 [N x K] -> fp16 m16n8k16 B-fragments ----------------
__global__ void permB_g(const float* __restrict__ src, uint4* __restrict__ outp,
                        int K, int kcnt, int Npad, int nValid) {
    int ktcnt = K >> 4;
    int total = (Npad >> 4) * ktcnt * 32;
    for (int i = blockIdx.x * blockDim.x + threadIdx.x; i < total; i += gridDim.x * blockDim.x) {
        int lane = i & 31;
        int kt = (i >> 5) % ktcnt;
        int nt2 = (i >> 5) / ktcnt;
        int g = lane >> 2, q = lane & 3;
        int na = nt2 * 16 + g;
        int nb8 = na + 8;
        int c0 = kt * 16 + 2 * q;
        float2 a0 = make_float2(0.f, 0.f), a1 = a0, b0 = a0, b1 = a0;
        if (na < nValid) {
            const float* p = src + (size_t)na * K + c0;
            a0 = *(const float2*)(p);
            a1 = *(const float2*)(p + 8);
        }
        if (nb8 < nValid) {
            const float* p = src + (size_t)nb8 * K + c0;
            b0 = *(const float2*)(p);
            b1 = *(const float2*)(p + 8);
        }
        uint4 o;
        o.x = pack2(a0.x, a0.y);
        o.y = pack2(a1.x, a1.y);
        o.z = pack2(b0.x, b0.y);
        o.w = pack2(b1.x, b1.y);
        int nbk = nt2 >> 4, tn2 = nt2 & 15, kc = kt >> 3, k16 = kt & 7;
        outp[((((nbk * kcnt + kc) * 8 + k16) * 16 + tn2) << 5) + lane] = o;
    }
}

// ---------------- shared fp16-mma mainloop (CTA 128x256, BK=128 chunks) ----------------
__device__ __forceinline__ void gemm_mainloop(const uint4* __restrict__ Asrc,
                                              const uint4* __restrict__ Bsrc,
                                              int nkt, char* st,
                                              int tid, int lane, int wm, int wn,
                                              float acc[4][4][4]) {
    uint32_t stb = smem_u32(st);
    auto prefetch = [&](int c) {
        uint32_t d = stb + (c & 1) * ST_BYTES;
        const uint4* a4 = Asrc + (size_t)c * 2048;
        const uint4* b4 = Bsrc + (size_t)c * 4096;
        #pragma unroll
        for (int i = 0; i < 4; i++)
            cp16(d + (tid + i * 512) * 16, a4 + tid + i * 512);
        uint32_t db = d + ST_A_BYTES;
        #pragma unroll
        for (int i = 0; i < 8; i++)
            cp16(db + (tid + i * 512) * 16, b4 + tid + i * 512);
        asm volatile("cp.async.commit_group;\n" ::: "memory");
    };

    #pragma unroll
    for (int mi = 0; mi < 4; mi++)
        #pragma unroll
        for (int ni = 0; ni < 4; ni++)
            #pragma unroll
            for (int r = 0; r < 4; r++) acc[mi][ni][r] = 0.f;

    prefetch(0);
    prefetch(1);

    for (int c = 0; c < nkt; c++) {
        if (c < nkt - 2)
            asm volatile("cp.async.wait_group 1;\n" ::: "memory");
        else
            asm volatile("cp.async.wait_group 0;\n" ::: "memory");
        __syncthreads();

        const uint4* SA = (const uint4*)(st + (c & 1) * ST_BYTES);     // [k16(8)][tm(8)][lane]
        const uint4* SB = SA + 2048;                                    // [k16(8)][tn2(16)][lane]

        #pragma unroll
        for (int k16 = 0; k16 < 8; k16++) {
            uint4 af[4], bf[2];
            #pragma unroll
            for (int mi = 0; mi < 4; mi++)
                af[mi] = SA[((k16 * 8 + wm * 4 + mi) << 5) + lane];
            #pragma unroll
            for (int n2 = 0; n2 < 2; n2++)
                bf[n2] = SB[((k16 * 16 + wn * 2 + n2) << 5) + lane];
            #pragma unroll
            for (int mi = 0; mi < 4; mi++)
                #pragma unroll
                for (int n2 = 0; n2 < 2; n2++) {
                    mma_f16(acc[mi][n2 * 2],     (const uint32_t*)&af[mi], bf[n2].x, bf[n2].y);
                    mma_f16(acc[mi][n2 * 2 + 1], (const uint32_t*)&af[mi], bf[n2].z, bf[n2].w);
                }
        }
        __syncthreads();
        if (c + 2 < nkt) prefetch(c + 2);
    }
}

// ---------------- K2: xg = gathered_emb @ W_ih^T (fp16 mma, fp32 out) ----------------
__global__ __launch_bounds__(512, 1)
void gemm_xg(const uint4* __restrict__ Ap, const uint4* __restrict__ Bp,
             float* __restrict__ xg) {
    extern __shared__ char st[];
    int tid = threadIdx.x, lane = tid & 31, warp = tid >> 5;
    int wm = warp >> 3, wn = warp & 7;
    int mb = blockIdx.x, nb = blockIdx.y;

    float acc[4][4][4];
    gemm_mainloop(Ap + (size_t)mb * 2 * 2048, Bp + (size_t)nb * 2 * 4096, 2,
                  st, tid, lane, wm, wn, acc);

    int g = lane >> 2, q = lane & 3;
    #pragma unroll
    for (int mi = 0; mi < 4; mi++) {
        int mA = mb * 128 + wm * 64 + mi * 16 + g;
        int mB = mA + 8;
        #pragma unroll
        for (int ni = 0; ni < 4; ni++) {
            int cc = wn * 32 + (ni >> 1) * 16 + (ni & 1) * 8 + q * 2;
            int n = nb * BN_ + cc;
            xg[(size_t)mA * G4_ + n]     = acc[mi][ni][0];
            xg[(size_t)mA * G4_ + n + 1] = acc[mi][ni][1];
            xg[(size_t)mB * G4_ + n]     = acc[mi][ni][2];
            xg[(size_t)mB * G4_ + n + 1] = acc[mi][ni][3];
        }
    }
}

// ---------------- K4: hid = hs @ W1^T + b1, epilogue writes K5 A-fragments directly ----------------
__global__ __launch_bounds__(512, 1)
void gemm_hid(const uint4* __restrict__ Ap, const uint4* __restrict__ Bp,
              const float* __restrict__ b1, uint4* __restrict__ outp) {
    __shared__ float b1s[BN_];
    extern __shared__ char st[];
    int tid = threadIdx.x, lane = tid & 31, warp = tid >> 5;
    int wm = warp >> 3, wn = warp & 7;
    int mb = blockIdx.x, nb = blockIdx.y;

    if (tid < BN_) b1s[tid] = b1[nb * BN_ + tid];

    float acc[4][4][4];
    gemm_mainloop(Ap + (size_t)mb * 4 * 2048, Bp + (size_t)nb * 4 * 4096, 4,
                  st, tid, lane, wm, wn, acc);

    int q = lane & 3;
    #pragma unroll
    for (int mi = 0; mi < 4; mi++) {
        int mA = mb * 128 + wm * 64 + mi * 16;   // tile base row
        int mb5 = mA >> 7, tm = (mA >> 4) & 7;
        #pragma unroll
        for (int j = 0; j < 2; j++) {
            int kt = nb * 16 + wn * 2 + j;       // n16 index = hid k16 index
            int kc = kt >> 3, k16 = kt & 7;
            int c = wn * 32 + j * 16 + 2 * q;    // local bias col
            float* L = acc[mi][2 * j];
            float* Hh = acc[mi][2 * j + 1];
            uint4 o;
            o.x = pack2(L[0] + b1s[c],      L[1] + b1s[c + 1]);
            o.y = pack2(L[2] + b1s[c],      L[3] + b1s[c + 1]);
            o.z = pack2(Hh[0] + b1s[c + 8], Hh[1] + b1s[c + 9]);
            o.w = pack2(Hh[2] + b1s[c + 8], Hh[3] + b1s[c + 9]);
            outp[((((mb5 * 8 + kc) * 8 + k16) * 8 + tm) << 5) + lane] = o;
        }
    }
}

// ---------------- K5: persistent logits = hid @ W2^T + b2 ----------------
// One CTA per SM; each CTA walks tiles bid, bid+G, ... with a rolling
// (tile, chunk) cp.async pipeline that never drains between tiles.
__global__ __launch_bounds__(512, 1)
void logits_persist(const uint4* __restrict__ Ap, const uint4* __restrict__ Bp,
                    const float* __restrict__ b2, float* __restrict__ out) {
    extern __shared__ char st[];
    uint32_t stb = smem_u32(st);
    int tid = threadIdx.x, lane = tid & 31, warp = tid >> 5;
    int wm = warp >> 3, wn = warp & 7;
    int bid = blockIdx.x, G = gridDim.x;

    int ntile = (NTILE_ - bid + G - 1) / G;
    int total = ntile * 8;

    auto prefetch = [&](int pos) {
        int t = bid + (pos >> 3) * G;
        int c = pos & 7;
        int mb = t & 15, nb = t >> 4;
        const uint4* a4 = Ap + ((size_t)mb * 8 + c) * 2048;
        const uint4* b4 = Bp + ((size_t)nb * 8 + c) * 4096;
        uint32_t d = stb + (pos & 1) * ST_BYTES;
        #pragma unroll
        for (int i = 0; i < 4; i++)
            cp16(d + (tid + i * 512) * 16, a4 + tid + i * 512);
        uint32_t db = d + ST_A_BYTES;
        #pragma unroll
        for (int i = 0; i < 8; i++)
            cp16(db + (tid + i * 512) * 16, b4 + tid + i * 512);
        asm volatile("cp.async.commit_group;\n" ::: "memory");
    };

    float acc[4][4][4];
    #pragma unroll
    for (int mi = 0; mi < 4; mi++)
        #pragma unroll
        for (int ni = 0; ni < 4; ni++)
            #pragma unroll
            for (int r = 0; r < 4; r++) acc[mi][ni][r] = 0.f;

    prefetch(0);
    prefetch(1);

    int g = lane >> 2, q = lane & 3;

    for (int pos = 0; pos < total; pos++) {
        if (pos < total - 2)
            asm volatile("cp.async.wait_group 1;\n" ::: "memory");
        else
            asm volatile("cp.async.wait_group 0;\n" ::: "memory");
        __syncthreads();

        const uint4* SA = (const uint4*)(st + (pos & 1) * ST_BYTES);   // [k16(8)][tm(8)][lane]
        const uint4* SB = SA + 2048;                                    // [k16(8)][tn2(16)][lane]

        #pragma unroll
        for (int k16 = 0; k16 < 8; k16++) {
            uint4 af[4], bf[2];
            #pragma unroll
            for (int mi = 0; mi < 4; mi++)
                af[mi] = SA[((k16 * 8 + wm * 4 + mi) << 5) + lane];
            #pragma unroll
            for (int n2 = 0; n2 < 2; n2++)
                bf[n2] = SB[((k16 * 16 + wn * 2 + n2) << 5) + lane];
            #pragma unroll
            for (int mi = 0; mi < 4; mi++)
                #pragma unroll
                for (int n2 = 0; n2 < 2; n2++) {
                    mma_f16(acc[mi][n2 * 2],     (const uint32_t*)&af[mi], bf[n2].x, bf[n2].y);
                    mma_f16(acc[mi][n2 * 2 + 1], (const uint32_t*)&af[mi], bf[n2].z, bf[n2].w);
                }
        }
        __syncthreads();
        if (pos + 2 < total) prefetch(pos + 2);   // next tile's loads fly during epilogue

        if ((pos & 7) == 7) {
            int t = bid + (pos >> 3) * G;
            int mb = t & 15, nb = t >> 4;
            #pragma unroll
            for (int mi = 0; mi < 4; mi++) {
                int mA = mb * 128 + wm * 64 + mi * 16 + g;
                int mB = mA + 8;
                size_t offA = ((size_t)(mA & 31) * T_ + (size_t)(mA >> 5)) * (size_t)V_;
                size_t offB = ((size_t)(mB & 31) * T_ + (size_t)(mB >> 5)) * (size_t)V_;
                #pragma unroll
                for (int ni = 0; ni < 4; ni++) {
                    int cc = wn * 32 + (ni >> 1) * 16 + (ni & 1) * 8 + q * 2;
                    int n = nb * BN_ + cc;
                    if (n < V_) {
                        float bv0 = __ldg(b2 + n);
                        out[offA + n] = acc[mi][ni][0] + bv0;
                        out[offB + n] = acc[mi][ni][2] + bv0;
                        if (n + 1 < V_) {
                            float bv1 = __ldg(b2 + n + 1);
                            out[offA + n + 1] = acc[mi][ni][1] + bv1;
                            out[offB + n + 1] = acc[mi][ni][3] + bv1;
                        }
                    }
                    #pragma unroll
                    for (int r = 0; r < 4; r++) acc[mi][ni][r] = 0.f;
                }
            }
        }
    }
}

// ---------------- launch ----------------
extern "C" void kernel_launch(void* const* d_in, const int* in_sizes, int n_in,
                              void* d_out, int out_size) {
    const float* features = (const float*)d_in[0];
    const int*   captions = (const int*)d_in[1];
    const float* emb      = (const float*)d_in[2];
    const float* W_ih     = (const float*)d_in[3];
    const float* W_hh     = (const float*)d_in[4];
    const float* b_ih     = (const float*)d_in[5];
    const float* b_hh     = (const float*)d_in[6];
    const float* W1       = (const float*)d_in[7];
    const float* b1       = (const float*)d_in[8];
    const float* W2       = (const float*)d_in[9];
    const float* b2       = (const float*)d_in[10];
    float* out = (float*)d_out;

    void *p_base, *p_xg, *p_hs, *p_embp, *p_wihp, *p_hsp, *p_w1p, *p_hidp, *p_w2p;
    cudaGetSymbolAddress(&p_base, g_base);
    cudaGetSymbolAddress(&p_xg,   g_xg);
    cudaGetSymbolAddress(&p_hs,   g_hs);
    cudaGetSymbolAddress(&p_embp, g_embp);
    cudaGetSymbolAddress(&p_wihp, g_wihp);
    cudaGetSymbolAddress(&p_hsp,  g_hsp);
    cudaGetSymbolAddress(&p_w1p,  g_w1p);
    cudaGetSymbolAddress(&p_hidp, g_hidp);
    cudaGetSymbolAddress(&p_w2p,  g_w2p);
    float* base = (float*)p_base;
    float* xg   = (float*)p_xg;
    float* hs   = (float*)p_hs;

    cudaFuncSetAttribute(gemm_xg,        cudaFuncAttributeMaxDynamicSharedMemorySize, SMEM_DYN);
    cudaFuncSetAttribute(gemm_hid,       cudaFuncAttributeMaxDynamicSharedMemorySize, SMEM_DYN);
    cudaFuncSetAttribute(logits_persist, cudaFuncAttributeMaxDynamicSharedMemorySize, SMEM_DYN);

    // Streams/events for fork-join capture; SM count for the persistent grid.
    static cudaStream_t s2 = nullptr, s3 = nullptr;
    static cudaEvent_t evFork = nullptr, evJoin2 = nullptr, evJoin3 = nullptr;
    static int nsm = 0;
    if (s2 == nullptr) {
        cudaStreamCreateWithFlags(&s2, cudaStreamNonBlocking);
        cudaStreamCreateWithFlags(&s3, cudaStreamNonBlocking);
        cudaEventCreateWithFlags(&evFork,  cudaEventDisableTiming);
        cudaEventCreateWithFlags(&evJoin2, cudaEventDisableTiming);
        cudaEventCreateWithFlags(&evJoin3, cudaEventDisableTiming);
        int dev = 0;
        cudaGetDevice(&dev);
        cudaDeviceGetAttribute(&nsm, cudaDevAttrMultiProcessorCount, dev);
        if (nsm <= 0) nsm = 148;
    }

    // ---- fork ----
    cudaEventRecord(evFork, 0);
    cudaStreamWaitEvent(s2, evFork, 0);
    cudaStreamWaitEvent(s3, evFork, 0);

    // s2: W2 B-frag permute (only K5 depends on it)
    permB_g<<<4096, 256, 0, s2>>>(W2, (uint4*)p_w2p, H2_, 8, VPAD2_, V_);
    cudaEventRecord(evJoin2, s2);

    // s3: base gates + W1 B-frags (needed by lstm_scan / gemm_hid)
    base_kernel<<<B_, 256, 0, s3>>>(features, W_hh, b_ih, b_hh, base);
    permB_g<<<256, 256, 0, s3>>>(W1, (uint4*)p_w1p, H_, 4, H2_, H2_);
    cudaEventRecord(evJoin3, s3);

    // ---- main-stream chain ----
    permB_g<<<256, 256>>>(W_ih, (uint4*)p_wihp, E_, 2, G4_, G4_);
    permA_emb<<<256, 256>>>(emb, captions, (uint4*)p_embp);

    // K2: xg = emb_gathered @ W_ih^T  (fp16 mma)
    {
        dim3 grid(M_ / BM_, G4_ / BN_);   // (16, 8)
        gemm_xg<<<grid, 512, SMEM_DYN>>>((const uint4*)p_embp, (const uint4*)p_wihp, xg);
    }

    // join s3 (base + w1p) before the scan/K4 stage
    cudaStreamWaitEvent(0, evJoin3, 0);

    // K3: LSTM scan
    lstm_scan<<<128, 128>>>(xg, base, hs);

    // prep: hs A-frags (K=512, kcnt=4)
    permA_g<<<256, 256>>>(hs, (uint4*)p_hsp, M_, H_, 4);

    // K4: hid = hs @ W1^T + b1 -> writes K5 A-fragments directly (fp16)
    {
        dim3 grid(M_ / BM_, H2_ / BN_);   // (16, 4)
        gemm_hid<<<grid, 512, SMEM_DYN>>>((const uint4*)p_hsp, (const uint4*)p_w1p, b1,
                                          (uint4*)p_hidp);
    }

    // join s2 (w2p) before K5
    cudaStreamWaitEvent(0, evJoin2, 0);

    // K5: persistent logits
    {
        int grid = nsm < NTILE_ ? nsm : NTILE_;
        logits_persist<<<grid, 512, SMEM_DYN>>>((const uint4*)p_hidp, (const uint4*)p_w2p,
                                                b2, out);
    }
}

// round 15
// speedup vs baseline: 1.0565x; 1.0565x over previous
#include <cuda_runtime.h>
#include <cuda_fp16.h>
#include <cstdint>

// Problem constants
#define B_  32
#define T_  64
#define V_  50257
#define E_  256
#define H_  512
#define G4_ 2048   // 4*H
#define H2_ 1024   // 2*H
#define M_  2048   // T*B
#define VPAD2_ 50432  // 197*256 = 394*128

// K2/K4 mma tiling: CTA 128x256, 512 threads (16 warps 2x8), warp tile 64x32, BK=128
#define BM_ 128
#define BN_ 256
#define ST_A_BYTES 32768          // 128*128*2
#define ST_B_BYTES 65536          // 256*128*2
#define ST_BYTES   98304
#define SMEM_DYN   (2 * ST_BYTES) // 196608

// K5 tiling: CTA 128x128, 256 threads (8 warps 4x2), warp tile 32x64, BK=64, 2 CTAs/SM
#define K5_ST_BYTES 32768         // A 16KB + B 16KB
#define K5_SMEM     (2 * K5_ST_BYTES)   // 65536

// ---------------- scratch (device globals; no allocation allowed) ----------------
__device__ float g_base[B_ * G4_];
__device__ float g_xg[M_ * G4_];
__device__ float g_hs[M_ * H_];
__device__ __align__(16) __half g_embp[(size_t)M_ * E_];            // gathered emb A-frags (K2)
__device__ __align__(16) __half g_wihp[(size_t)G4_ * E_];           // W_ih B-frags (K2)
__device__ __align__(16) __half g_hsp[(size_t)M_ * H_];             // hs A-frags (K4)
__device__ __align__(16) __half g_w1p[(size_t)H2_ * H_];            // W1 B-frags (K4)
__device__ __align__(16) __half g_hidp[(size_t)M_ * H2_];           // hid A-frags (K5), written by K4
__device__ __align__(16) __half g_w2p[(size_t)VPAD2_ * H2_];        // W2 B-frags (K5)

// ---------------- helpers ----------------
__device__ __forceinline__ void mma_f16(float* d, const uint32_t* a, uint32_t b0, uint32_t b1) {
    asm volatile(
        "mma.sync.aligned.m16n8k16.row.col.f32.f16.f16.f32 "
        "{%0,%1,%2,%3}, {%4,%5,%6,%7}, {%8,%9}, {%0,%1,%2,%3};\n"
        : "+f"(d[0]), "+f"(d[1]), "+f"(d[2]), "+f"(d[3])
        : "r"(a[0]), "r"(a[1]), "r"(a[2]), "r"(a[3]), "r"(b0), "r"(b1));
}

__device__ __forceinline__ float sigf(float x) {
    return __fdividef(1.f, 1.f + __expf(-x));
}
__device__ __forceinline__ float ftanh(float x) {
    float e = __expf(2.f * x);
    return 1.f - __fdividef(2.f, e + 1.f);
}

__device__ __forceinline__ uint32_t smem_u32(const void* p) {
    return (uint32_t)__cvta_generic_to_shared(p);
}

__device__ __forceinline__ void cp16(uint32_t dst, const void* src) {
    asm volatile("cp.async.cg.shared.global [%0], [%1], 16;\n"
                 :: "r"(dst), "l"(src) : "memory");
}

__device__ __forceinline__ uint32_t pack2(float lo, float hi) {
    __half2 h = __floats2half2_rn(lo, hi);
    return *(uint32_t*)&h;
}

// ---------------- K1: base gates = features @ W_hh^T + b_ih + b_hh ----------------
__global__ void base_kernel(const float* __restrict__ feat,
                            const float* __restrict__ W_hh,
                            const float* __restrict__ b_ih,
                            const float* __restrict__ b_hh,
                            float* __restrict__ base) {
    __shared__ float4 f4[H_ / 4];
    int b = blockIdx.x;
    if (threadIdx.x < H_ / 4)
        f4[threadIdx.x] = ((const float4*)(feat + (size_t)b * H_))[threadIdx.x];
    __syncthreads();
    for (int g = threadIdx.x; g < G4_; g += blockDim.x) {
        const float4* w4 = (const float4*)(W_hh + (size_t)g * H_);
        float s = 0.f;
        #pragma unroll 8
        for (int k = 0; k < H_ / 4; k++) {
            float4 w = w4[k], f = f4[k];
            s += w.x * f.x + w.y * f.y + w.z * f.z + w.w * f.w;
        }
        base[b * G4_ + g] = s + b_ih[g] + b_hh[g];
    }
}

// ---------------- K3: LSTM scan (depth-8 prefetch) ----------------
__global__ void lstm_scan(const float* __restrict__ xg,
                          const float* __restrict__ base,
                          float* __restrict__ hs) {
    int idx = blockIdx.x * blockDim.x + threadIdx.x;
    int b = idx >> 9, h = idx & 511;
    float bi = base[b * G4_ + h];
    float bff = base[b * G4_ + H_ + h];
    float bg = base[b * G4_ + 2 * H_ + h];
    float bo = base[b * G4_ + 3 * H_ + h];

    const float* xr = xg + (size_t)b * G4_ + h;
    const size_t step = (size_t)B_ * G4_;

    float4 pf[8];
    #pragma unroll
    for (int j = 0; j < 8; j++) {
        const float* p = xr + (size_t)j * step;
        pf[j] = make_float4(p[0], p[H_], p[2 * H_], p[3 * H_]);
    }

    float c = 0.f;
    float* hp = hs + (size_t)b * H_ + h;
    #pragma unroll 8
    for (int t = 0; t < T_; t++) {
        float4 cur = pf[t & 7];
        if (t + 8 < T_) {
            const float* p = xr + (size_t)(t + 8) * step;
            pf[t & 7] = make_float4(p[0], p[H_], p[2 * H_], p[3 * H_]);
        }
        float i = sigf(cur.x + bi);
        float f = sigf(cur.y + bff);
        float g = ftanh(cur.z + bg);
        float o = sigf(cur.w + bo);
        c = f * c + i * g;
        hp[(size_t)t * B_ * H_] = o * ftanh(c);
    }
}

// ---------------- generic A-perm: fp32 [M x K] -> fp16 m16n8k16 A-fragments ----------------
__global__ void permA_g(const float* __restrict__ src, uint4* __restrict__ outp,
                        int M, int K, int kcnt) {
    int ktcnt = K >> 4;
    int total = (M >> 4) * ktcnt * 32;
    for (int i = blockIdx.x * blockDim.x + threadIdx.x; i < total; i += gridDim.x * blockDim.x) {
        int lane = i & 31;
        int kt = (i >> 5) % ktcnt;
        int mt = (i >> 5) / ktcnt;
        int g = lane >> 2, q = lane & 3;
        int r0 = mt * 16 + g, r1 = r0 + 8;
        int c0 = kt * 16 + 2 * q;
        const float* p0 = src + (size_t)r0 * K + c0;
        const float* p1 = src + (size_t)r1 * K + c0;
        float2 v0 = *(const float2*)(p0);
        float2 v1 = *(const float2*)(p1);
        float2 v2 = *(const float2*)(p0 + 8);
        float2 v3 = *(const float2*)(p1 + 8);
        uint4 o;
        o.x = pack2(v0.x, v0.y);
        o.y = pack2(v1.x, v1.y);
        o.z = pack2(v2.x, v2.y);
        o.w = pack2(v3.x, v3.y);
        int mb = mt >> 3, tm = mt & 7, kc = kt >> 3, k16 = kt & 7;
        outp[((((mb * kcnt + kc) * 8 + k16) * 8 + tm) << 5) + lane] = o;
    }
}

// ---------------- gathered emb A-perm (K2): rows are emb[tok(m)] ----------------
__global__ void permA_emb(const float* __restrict__ emb, const int* __restrict__ captions,
                          uint4* __restrict__ outp) {
    const int K = E_, ktcnt = E_ / 16, kcnt = E_ / 128;   // 16, 2
    int total = (M_ / 16) * ktcnt * 32;
    for (int i = blockIdx.x * blockDim.x + threadIdx.x; i < total; i += gridDim.x * blockDim.x) {
        int lane = i & 31;
        int kt = (i >> 5) % ktcnt;
        int mt = (i >> 5) / ktcnt;
        int g = lane >> 2, q = lane & 3;
        int m0 = mt * 16 + g, m1 = m0 + 8;
        int c0 = kt * 16 + 2 * q;
        int b0 = m0 & 31, t0 = m0 >> 5;
        int b1 = m1 & 31, t1 = m1 >> 5;
        int tok0 = captions[b0 * T_ + (t0 ? t0 - 1 : 0)];
        int tok1 = captions[b1 * T_ + (t1 ? t1 - 1 : 0)];
        const float* p0 = emb + (size_t)tok0 * K + c0;
        const float* p1 = emb + (size_t)tok1 * K + c0;
        float2 v0 = *(const float2*)(p0);
        float2 v1 = *(const float2*)(p1);
        float2 v2 = *(const float2*)(p0 + 8);
        float2 v3 = *(const float2*)(p1 + 8);
        uint4 o;
        o.x = pack2(v0.x, v0.y);
        o.y = pack2(v1.x, v1.y);
        o.z = pack2(v2.x, v2.y);
        o.w = pack2(v3.x, v3.y);
        int mb = mt >> 3, tm = mt & 7, kc = kt >> 3, k16 = kt & 7;
        outp[((((mb * kcnt + kc) * 8 + k16) * 8 + tm) << 5) + lane] = o;
    }
}

// ---------------- generic B-perm: fp32 [N x K] -> fp16 m16n8k16 B-fragments ----------------
__global__ void permB_g(const float* __restrict__ src, uint4* __restrict__ outp,
                        int K, int kcnt, int Npad, int nValid) {
    int ktcnt = K >> 4;
    int total = (Npad >> 4) * ktcnt * 32;
    for (int i = blockIdx.x * blockDim.x + threadIdx.x; i < total; i += gridDim.x * blockDim.x) {
        int lane = i & 31;
        int kt = (i >> 5) % ktcnt;
        int nt2 = (i >> 5) / ktcnt;
        int g = lane >> 2, q = lane & 3;
        int na = nt2 * 16 + g;
        int nb8 = na + 8;
        int c0 = kt * 16 + 2 * q;
        float2 a0 = make_float2(0.f, 0.f), a1 = a0, b0 = a0, b1 = a0;
        if (na < nValid) {
            const float* p = src + (size_t)na * K + c0;
            a0 = *(const float2*)(p);
            a1 = *(const float2*)(p + 8);
        }
        if (nb8 < nValid) {
            const float* p = src + (size_t)nb8 * K + c0;
            b0 = *(const float2*)(p);
            b1 = *(const float2*)(p + 8);
        }
        uint4 o;
        o.x = pack2(a0.x, a0.y);
        o.y = pack2(a1.x, a1.y);
        o.z = pack2(b0.x, b0.y);
        o.w = pack2(b1.x, b1.y);
        int nbk = nt2 >> 4, tn2 = nt2 & 15, kc = kt >> 3, k16 = kt & 7;
        outp[((((nbk * kcnt + kc) * 8 + k16) * 16 + tn2) << 5) + lane] = o;
    }
}

// ---------------- shared fp16-mma mainloop (CTA 128x256, BK=128 chunks) for K2/K4 ----------------
__device__ __forceinline__ void gemm_mainloop(const uint4* __restrict__ Asrc,
                                              const uint4* __restrict__ Bsrc,
                                              int nkt, char* st,
                                              int tid, int lane, int wm, int wn,
                                              float acc[4][4][4]) {
    uint32_t stb = smem_u32(st);
    auto prefetch = [&](int c) {
        uint32_t d = stb + (c & 1) * ST_BYTES;
        const uint4* a4 = Asrc + (size_t)c * 2048;
        const uint4* b4 = Bsrc + (size_t)c * 4096;
        #pragma unroll
        for (int i = 0; i < 4; i++)
            cp16(d + (tid + i * 512) * 16, a4 + tid + i * 512);
        uint32_t db = d + ST_A_BYTES;
        #pragma unroll
        for (int i = 0; i < 8; i++)
            cp16(db + (tid + i * 512) * 16, b4 + tid + i * 512);
        asm volatile("cp.async.commit_group;\n" ::: "memory");
    };

    #pragma unroll
    for (int mi = 0; mi < 4; mi++)
        #pragma unroll
        for (int ni = 0; ni < 4; ni++)
            #pragma unroll
            for (int r = 0; r < 4; r++) acc[mi][ni][r] = 0.f;

    prefetch(0);
    prefetch(1);

    for (int c = 0; c < nkt; c++) {
        if (c < nkt - 2)
            asm volatile("cp.async.wait_group 1;\n" ::: "memory");
        else
            asm volatile("cp.async.wait_group 0;\n" ::: "memory");
        __syncthreads();

        const uint4* SA = (const uint4*)(st + (c & 1) * ST_BYTES);     // [k16(8)][tm(8)][lane]
        const uint4* SB = SA + 2048;                                    // [k16(8)][tn2(16)][lane]

        #pragma unroll
        for (int k16 = 0; k16 < 8; k16++) {
            uint4 af[4], bf[2];
            #pragma unroll
            for (int mi = 0; mi < 4; mi++)
                af[mi] = SA[((k16 * 8 + wm * 4 + mi) << 5) + lane];
            #pragma unroll
            for (int n2 = 0; n2 < 2; n2++)
                bf[n2] = SB[((k16 * 16 + wn * 2 + n2) << 5) + lane];
            #pragma unroll
            for (int mi = 0; mi < 4; mi++)
                #pragma unroll
                for (int n2 = 0; n2 < 2; n2++) {
                    mma_f16(acc[mi][n2 * 2],     (const uint32_t*)&af[mi], bf[n2].x, bf[n2].y);
                    mma_f16(acc[mi][n2 * 2 + 1], (const uint32_t*)&af[mi], bf[n2].z, bf[n2].w);
                }
        }
        __syncthreads();
        if (c + 2 < nkt) prefetch(c + 2);
    }
}

// ---------------- K2: xg = gathered_emb @ W_ih^T (fp16 mma, fp32 out) ----------------
__global__ __launch_bounds__(512, 1)
void gemm_xg(const uint4* __restrict__ Ap, const uint4* __restrict__ Bp,
             float* __restrict__ xg) {
    extern __shared__ char st[];
    int tid = threadIdx.x, lane = tid & 31, warp = tid >> 5;
    int wm = warp >> 3, wn = warp & 7;
    int mb = blockIdx.x, nb = blockIdx.y;

    float acc[4][4][4];
    gemm_mainloop(Ap + (size_t)mb * 2 * 2048, Bp + (size_t)nb * 2 * 4096, 2,
                  st, tid, lane, wm, wn, acc);

    int g = lane >> 2, q = lane & 3;
    #pragma unroll
    for (int mi = 0; mi < 4; mi++) {
        int mA = mb * 128 + wm * 64 + mi * 16 + g;
        int mB = mA + 8;
        #pragma unroll
        for (int ni = 0; ni < 4; ni++) {
            int cc = wn * 32 + (ni >> 1) * 16 + (ni & 1) * 8 + q * 2;
            int n = nb * BN_ + cc;
            xg[(size_t)mA * G4_ + n]     = acc[mi][ni][0];
            xg[(size_t)mA * G4_ + n + 1] = acc[mi][ni][1];
            xg[(size_t)mB * G4_ + n]     = acc[mi][ni][2];
            xg[(size_t)mB * G4_ + n + 1] = acc[mi][ni][3];
        }
    }
}

// ---------------- K4: hid = hs @ W1^T + b1, epilogue writes K5 A-fragments directly ----------------
__global__ __launch_bounds__(512, 1)
void gemm_hid(const uint4* __restrict__ Ap, const uint4* __restrict__ Bp,
              const float* __restrict__ b1, uint4* __restrict__ outp) {
    __shared__ float b1s[BN_];
    extern __shared__ char st[];
    int tid = threadIdx.x, lane = tid & 31, warp = tid >> 5;
    int wm = warp >> 3, wn = warp & 7;
    int mb = blockIdx.x, nb = blockIdx.y;

    if (tid < BN_) b1s[tid] = b1[nb * BN_ + tid];

    float acc[4][4][4];
    gemm_mainloop(Ap + (size_t)mb * 4 * 2048, Bp + (size_t)nb * 4 * 4096, 4,
                  st, tid, lane, wm, wn, acc);

    int q = lane & 3;
    #pragma unroll
    for (int mi = 0; mi < 4; mi++) {
        int mA = mb * 128 + wm * 64 + mi * 16;   // tile base row
        int mb5 = mA >> 7, tm = (mA >> 4) & 7;
        #pragma unroll
        for (int j = 0; j < 2; j++) {
            int kt = nb * 16 + wn * 2 + j;       // n16 index = hid k16 index
            int kc = kt >> 3, k16 = kt & 7;
            int c = wn * 32 + j * 16 + 2 * q;    // local bias col
            float* L = acc[mi][2 * j];
            float* Hh = acc[mi][2 * j + 1];
            uint4 o;
            o.x = pack2(L[0] + b1s[c],      L[1] + b1s[c + 1]);
            o.y = pack2(L[2] + b1s[c],      L[3] + b1s[c + 1]);
            o.z = pack2(Hh[0] + b1s[c + 8], Hh[1] + b1s[c + 9]);
            o.w = pack2(Hh[2] + b1s[c + 8], Hh[3] + b1s[c + 9]);
            outp[((((mb5 * 8 + kc) * 8 + k16) * 8 + tm) << 5) + lane] = o;
        }
    }
}

// ---------------- K5: logits = hid @ W2^T + b2 (128x128 CTA, 2 CTAs/SM) ----------------
// 256 threads, 8 warps (wm 0..3 x wn 0..1), warp tile 32x64, BK=64, double buffer.
__global__ __launch_bounds__(256, 2)
void logits_mma2(const uint4* __restrict__ Ap, const uint4* __restrict__ Bp,
                 const float* __restrict__ b2, float* __restrict__ out) {
    __shared__ float b2s[128];
    extern __shared__ char st[];
    uint32_t stb = smem_u32(st);
    int tid = threadIdx.x, lane = tid & 31, warp = tid >> 5;
    int wm = warp >> 1;       // 0..3 (M)
    int wn = warp & 1;        // 0..1 (N)
    int mb = blockIdx.x;      // 0..15
    int nb = blockIdx.y;      // 0..393 (128-wide N blocks)

    if (tid < 128) { int v = nb * 128 + tid; b2s[tid] = (v < V_) ? b2[v] : 0.f; }

    int nbk = nb >> 1;            // 256-wide block in B-frag layout
    int tnb = (nb & 1) * 8;       // tn2 half offset

    // chunk c (0..15, 64-K each): kc = c>>1, k16 base = (c&1)*4
    auto prefetch = [&](int c) {
        uint32_t d = stb + (c & 1) * K5_ST_BYTES;
        int kc = c >> 1, k16b = (c & 1) * 4;
        // A: contiguous 1024 uint4 (4 k16 x 8 tm x 32 lanes)
        const uint4* a4 = Ap + ((size_t)((mb * 8 + kc) * 8 + k16b)) * 256;
        #pragma unroll
        for (int j = 0; j < 4; j++)
            cp16(d + (tid + j * 256) * 16, a4 + tid + j * 256);
        // B: 4 pieces of 256 uint4 (per k16: half of the tn2 range)
        uint32_t db = d + 16384;
        #pragma unroll
        for (int k = 0; k < 4; k++) {
            const uint4* b4 = Bp + ((size_t)(((nbk * 8 + kc) * 8 + (k16b + k)) * 16 + tnb)) * 32;
            cp16(db + (k * 256 + tid) * 16, b4 + tid);
        }
        asm volatile("cp.async.commit_group;\n" ::: "memory");
    };

    float acc[2][8][4];
    #pragma unroll
    for (int mi = 0; mi < 2; mi++)
        #pragma unroll
        for (int ni = 0; ni < 8; ni++)
            #pragma unroll
            for (int r = 0; r < 4; r++) acc[mi][ni][r] = 0.f;

    prefetch(0);
    prefetch(1);

    for (int c = 0; c < 16; c++) {
        if (c < 14)
            asm volatile("cp.async.wait_group 1;\n" ::: "memory");
        else
            asm volatile("cp.async.wait_group 0;\n" ::: "memory");
        __syncthreads();

        const uint4* SA = (const uint4*)(st + (c & 1) * K5_ST_BYTES);  // [k16l(4)][tm(8)][lane]
        const uint4* SB = SA + 1024;                                    // [k16l(4)][tn(8)][lane]

        #pragma unroll
        for (int k16l = 0; k16l < 4; k16l++) {
            uint4 af[2], bf[4];
            #pragma unroll
            for (int mi = 0; mi < 2; mi++)
                af[mi] = SA[((k16l * 8 + wm * 2 + mi) << 5) + lane];
            #pragma unroll
            for (int n2 = 0; n2 < 4; n2++)
                bf[n2] = SB[((k16l * 8 + wn * 4 + n2) << 5) + lane];
            #pragma unroll
            for (int mi = 0; mi < 2; mi++)
                #pragma unroll
                for (int n2 = 0; n2 < 4; n2++) {
                    mma_f16(acc[mi][n2 * 2],     (const uint32_t*)&af[mi], bf[n2].x, bf[n2].y);
                    mma_f16(acc[mi][n2 * 2 + 1], (const uint32_t*)&af[mi], bf[n2].z, bf[n2].w);
                }
        }
        __syncthreads();
        if (c + 2 < 16) prefetch(c + 2);
    }

    // epilogue: m = t*B+b ; out[b][t][v]
    int g = lane >> 2, q = lane & 3;
    #pragma unroll
    for (int mi = 0; mi < 2; mi++) {
        int mA = mb * 128 + wm * 32 + mi * 16 + g;
        int mB = mA + 8;
        size_t offA = ((size_t)(mA & 31) * T_ + (size_t)(mA >> 5)) * (size_t)V_;
        size_t offB = ((size_t)(mB & 31) * T_ + (size_t)(mB >> 5)) * (size_t)V_;
        #pragma unroll
        for (int ni = 0; ni < 8; ni++) {
            int n2 = ni >> 1, h8 = ni & 1;
            int cc = wn * 64 + n2 * 16 + h8 * 8 + q * 2;
            int n = nb * 128 + cc;
            if (n < V_) {
                out[offA + n] = acc[mi][ni][0] + b2s[cc];
                out[offB + n] = acc[mi][ni][2] + b2s[cc];
                if (n + 1 < V_) {
                    out[offA + n + 1] = acc[mi][ni][1] + b2s[cc + 1];
                    out[offB + n + 1] = acc[mi][ni][3] + b2s[cc + 1];
                }
            }
        }
    }
}

// ---------------- launch ----------------
extern "C" void kernel_launch(void* const* d_in, const int* in_sizes, int n_in,
                              void* d_out, int out_size) {
    const float* features = (const float*)d_in[0];
    const int*   captions = (const int*)d_in[1];
    const float* emb      = (const float*)d_in[2];
    const float* W_ih     = (const float*)d_in[3];
    const float* W_hh     = (const float*)d_in[4];
    const float* b_ih     = (const float*)d_in[5];
    const float* b_hh     = (const float*)d_in[6];
    const float* W1       = (const float*)d_in[7];
    const float* b1       = (const float*)d_in[8];
    const float* W2       = (const float*)d_in[9];
    const float* b2       = (const float*)d_in[10];
    float* out = (float*)d_out;

    void *p_base, *p_xg, *p_hs, *p_embp, *p_wihp, *p_hsp, *p_w1p, *p_hidp, *p_w2p;
    cudaGetSymbolAddress(&p_base, g_base);
    cudaGetSymbolAddress(&p_xg,   g_xg);
    cudaGetSymbolAddress(&p_hs,   g_hs);
    cudaGetSymbolAddress(&p_embp, g_embp);
    cudaGetSymbolAddress(&p_wihp, g_wihp);
    cudaGetSymbolAddress(&p_hsp,  g_hsp);
    cudaGetSymbolAddress(&p_w1p,  g_w1p);
    cudaGetSymbolAddress(&p_hidp, g_hidp);
    cudaGetSymbolAddress(&p_w2p,  g_w2p);
    float* base = (float*)p_base;
    float* xg   = (float*)p_xg;
    float* hs   = (float*)p_hs;

    cudaFuncSetAttribute(gemm_xg,     cudaFuncAttributeMaxDynamicSharedMemorySize, SMEM_DYN);
    cudaFuncSetAttribute(gemm_hid,    cudaFuncAttributeMaxDynamicSharedMemorySize, SMEM_DYN);
    cudaFuncSetAttribute(logits_mma2, cudaFuncAttributeMaxDynamicSharedMemorySize, K5_SMEM);

    // Streams/events for fork-join capture.
    static cudaStream_t s2 = nullptr, s3 = nullptr;
    static cudaEvent_t evFork = nullptr, evJoin2 = nullptr, evJoin3 = nullptr;
    if (s2 == nullptr) {
        cudaStreamCreateWithFlags(&s2, cudaStreamNonBlocking);
        cudaStreamCreateWithFlags(&s3, cudaStreamNonBlocking);
        cudaEventCreateWithFlags(&evFork,  cudaEventDisableTiming);
        cudaEventCreateWithFlags(&evJoin2, cudaEventDisableTiming);
        cudaEventCreateWithFlags(&evJoin3, cudaEventDisableTiming);
    }

    // ---- fork ----
    cudaEventRecord(evFork, 0);
    cudaStreamWaitEvent(s2, evFork, 0);
    cudaStreamWaitEvent(s3, evFork, 0);

    // s2: W2 B-frag permute (only K5 depends on it)
    permB_g<<<4096, 256, 0, s2>>>(W2, (uint4*)p_w2p, H2_, 8, VPAD2_, V_);
    cudaEventRecord(evJoin2, s2);

    // s3: base gates + W1 B-frags (needed by lstm_scan / gemm_hid)
    base_kernel<<<B_, 256, 0, s3>>>(features, W_hh, b_ih, b_hh, base);
    permB_g<<<256, 256, 0, s3>>>(W1, (uint4*)p_w1p, H_, 4, H2_, H2_);
    cudaEventRecord(evJoin3, s3);

    // ---- main-stream chain ----
    permB_g<<<256, 256>>>(W_ih, (uint4*)p_wihp, E_, 2, G4_, G4_);
    permA_emb<<<256, 256>>>(emb, captions, (uint4*)p_embp);

    // K2: xg = emb_gathered @ W_ih^T  (fp16 mma)
    {
        dim3 grid(M_ / BM_, G4_ / BN_);   // (16, 8)
        gemm_xg<<<grid, 512, SMEM_DYN>>>((const uint4*)p_embp, (const uint4*)p_wihp, xg);
    }

    // join s3 (base + w1p) before the scan/K4 stage
    cudaStreamWaitEvent(0, evJoin3, 0);

    // K3: LSTM scan
    lstm_scan<<<128, 128>>>(xg, base, hs);

    // prep: hs A-frags (K=512, kcnt=4)
    permA_g<<<256, 256>>>(hs, (uint4*)p_hsp, M_, H_, 4);

    // K4: hid = hs @ W1^T + b1 -> writes K5 A-fragments directly (fp16)
    {
        dim3 grid(M_ / BM_, H2_ / BN_);   // (16, 4)
        gemm_hid<<<grid, 512, SMEM_DYN>>>((const uint4*)p_hsp, (const uint4*)p_w1p, b1,
                                          (uint4*)p_hidp);
    }

    // join s2 (w2p) before K5
    cudaStreamWaitEvent(0, evJoin2, 0);

    // K5: logits, 128x128 tiles, 2 CTAs/SM
    {
        dim3 grid(M_ / 128, VPAD2_ / 128);   // (16, 394)
        logits_mma2<<<grid, 256, K5_SMEM>>>((const uint4*)p_hidp, (const uint4*)p_w2p, b2, out);
    }
}

// round 16
// speedup vs baseline: 1.4066x; 1.3314x over previous
#include <cuda_runtime.h>
#include <cuda_fp16.h>
#include <cstdint>

// Problem constants
#define B_  32
#define T_  64
#define V_  50257
#define E_  256
#define H_  512
#define G4_ 2048   // 4*H
#define H2_ 1024   // 2*H
#define M_  2048   // T*B
#define VPAD2_ 50432  // 197*256

// mma tiling: CTA 128x256, 512 threads (16 warps 2x8), warp tile 64x32, BK=128
#define BM_ 128
#define BN_ 256
#define ST_A_BYTES 32768          // 128*128*2
#define ST_B_BYTES 65536          // 256*128*2
#define ST_BYTES   98304
#define SMEM_DYN   (2 * ST_BYTES) // 196608

// ---------------- scratch (device globals; no allocation allowed) ----------------
__device__ float g_base[B_ * G4_];
__device__ float g_xg[M_ * G4_];
__device__ float g_hs[M_ * H_];
__device__ float g_b2p[VPAD2_];                                     // b2 + W2@b1
__device__ __align__(16) __half g_embp[(size_t)M_ * E_];            // gathered emb A-frags (K2)
__device__ __align__(16) __half g_wihp[(size_t)G4_ * E_];           // W_ih B-frags (K2)
__device__ __align__(16) __half g_hsp[(size_t)M_ * H_];             // hs A-frags (K5')
__device__ __align__(16) __half g_w1t[(size_t)H_ * H2_];            // W1^T B-frags (Wc gemm)
__device__ __align__(16) __half g_w2a[(size_t)VPAD2_ * H2_];        // W2 A-frags (Wc gemm)
__device__ __align__(16) __half g_wcp[(size_t)VPAD2_ * H_];         // Wc B-frags (K5'), by gemm_wc

// ---------------- helpers ----------------
__device__ __forceinline__ void mma_f16(float* d, const uint32_t* a, uint32_t b0, uint32_t b1) {
    asm volatile(
        "mma.sync.aligned.m16n8k16.row.col.f32.f16.f16.f32 "
        "{%0,%1,%2,%3}, {%4,%5,%6,%7}, {%8,%9}, {%0,%1,%2,%3};\n"
        : "+f"(d[0]), "+f"(d[1]), "+f"(d[2]), "+f"(d[3])
        : "r"(a[0]), "r"(a[1]), "r"(a[2]), "r"(a[3]), "r"(b0), "r"(b1));
}

__device__ __forceinline__ float sigf(float x) {
    return __fdividef(1.f, 1.f + __expf(-x));
}
__device__ __forceinline__ float ftanh(float x) {
    float e = __expf(2.f * x);
    return 1.f - __fdividef(2.f, e + 1.f);
}

__device__ __forceinline__ uint32_t smem_u32(const void* p) {
    return (uint32_t)__cvta_generic_to_shared(p);
}

__device__ __forceinline__ void cp16(uint32_t dst, const void* src) {
    asm volatile("cp.async.cg.shared.global [%0], [%1], 16;\n"
                 :: "r"(dst), "l"(src) : "memory");
}

__device__ __forceinline__ uint32_t pack2(float lo, float hi) {
    __half2 h = __floats2half2_rn(lo, hi);
    return *(uint32_t*)&h;
}

// ---------------- K1: base gates = features @ W_hh^T + b_ih + b_hh ----------------
__global__ void base_kernel(const float* __restrict__ feat,
                            const float* __restrict__ W_hh,
                            const float* __restrict__ b_ih,
                            const float* __restrict__ b_hh,
                            float* __restrict__ base) {
    __shared__ float4 f4[H_ / 4];
    int b = blockIdx.x;
    if (threadIdx.x < H_ / 4)
        f4[threadIdx.x] = ((const float4*)(feat + (size_t)b * H_))[threadIdx.x];
    __syncthreads();
    for (int g = threadIdx.x; g < G4_; g += blockDim.x) {
        const float4* w4 = (const float4*)(W_hh + (size_t)g * H_);
        float s = 0.f;
        #pragma unroll 8
        for (int k = 0; k < H_ / 4; k++) {
            float4 w = w4[k], f = f4[k];
            s += w.x * f.x + w.y * f.y + w.z * f.z + w.w * f.w;
        }
        base[b * G4_ + g] = s + b_ih[g] + b_hh[g];
    }
}

// ---------------- b2' = b2 + W2 @ b1 (warp per row, deterministic) ----------------
__global__ void bias2_kernel(const float* __restrict__ W2, const float* __restrict__ b1,
                             const float* __restrict__ b2, float* __restrict__ b2p) {
    int w = (blockIdx.x * blockDim.x + threadIdx.x) >> 5;
    int lane = threadIdx.x & 31;
    if (w >= V_) return;
    const float4* row = (const float4*)(W2 + (size_t)w * H2_);
    const float4* bb = (const float4*)b1;
    float s = 0.f;
    #pragma unroll
    for (int j = 0; j < 8; j++) {
        float4 a = row[lane + j * 32], c = bb[lane + j * 32];
        s += a.x * c.x + a.y * c.y + a.z * c.z + a.w * c.w;
    }
    #pragma unroll
    for (int o = 16; o; o >>= 1) s += __shfl_xor_sync(0xFFFFFFFFu, s, o);
    if (lane == 0) b2p[w] = s + b2[w];
}

// ---------------- K3: LSTM scan (depth-8 prefetch) ----------------
__global__ void lstm_scan(const float* __restrict__ xg,
                          const float* __restrict__ base,
                          float* __restrict__ hs) {
    int idx = blockIdx.x * blockDim.x + threadIdx.x;
    int b = idx >> 9, h = idx & 511;
    float bi = base[b * G4_ + h];
    float bff = base[b * G4_ + H_ + h];
    float bg = base[b * G4_ + 2 * H_ + h];
    float bo = base[b * G4_ + 3 * H_ + h];

    const float* xr = xg + (size_t)b * G4_ + h;
    const size_t step = (size_t)B_ * G4_;

    float4 pf[8];
    #pragma unroll
    for (int j = 0; j < 8; j++) {
        const float* p = xr + (size_t)j * step;
        pf[j] = make_float4(p[0], p[H_], p[2 * H_], p[3 * H_]);
    }

    float c = 0.f;
    float* hp = hs + (size_t)b * H_ + h;
    #pragma unroll 8
    for (int t = 0; t < T_; t++) {
        float4 cur = pf[t & 7];
        if (t + 8 < T_) {
            const float* p = xr + (size_t)(t + 8) * step;
            pf[t & 7] = make_float4(p[0], p[H_], p[2 * H_], p[3 * H_]);
        }
        float i = sigf(cur.x + bi);
        float f = sigf(cur.y + bff);
        float g = ftanh(cur.z + bg);
        float o = sigf(cur.w + bo);
        c = f * c + i * g;
        hp[(size_t)t * B_ * H_] = o * ftanh(c);
    }
}

// ---------------- generic A-perm: fp32 [M x K] -> fp16 m16n8k16 A-fragments (row-padded) ----------------
__global__ void permA_g(const float* __restrict__ src, uint4* __restrict__ outp,
                        int Mpad, int K, int kcnt, int nValid) {
    int ktcnt = K >> 4;
    int total = (Mpad >> 4) * ktcnt * 32;
    for (int i = blockIdx.x * blockDim.x + threadIdx.x; i < total; i += gridDim.x * blockDim.x) {
        int lane = i & 31;
        int kt = (i >> 5) % ktcnt;
        int mt = (i >> 5) / ktcnt;
        int g = lane >> 2, q = lane & 3;
        int r0 = mt * 16 + g, r1 = r0 + 8;
        int c0 = kt * 16 + 2 * q;
        float2 v0 = make_float2(0.f, 0.f), v1 = v0, v2 = v0, v3 = v0;
        if (r0 < nValid) {
            const float* p0 = src + (size_t)r0 * K + c0;
            v0 = *(const float2*)(p0);
            v2 = *(const float2*)(p0 + 8);
        }
        if (r1 < nValid) {
            const float* p1 = src + (size_t)r1 * K + c0;
            v1 = *(const float2*)(p1);
            v3 = *(const float2*)(p1 + 8);
        }
        uint4 o;
        o.x = pack2(v0.x, v0.y);
        o.y = pack2(v1.x, v1.y);
        o.z = pack2(v2.x, v2.y);
        o.w = pack2(v3.x, v3.y);
        int mb = mt >> 3, tm = mt & 7, kc = kt >> 3, k16 = kt & 7;
        outp[((((mb * kcnt + kc) * 8 + k16) * 8 + tm) << 5) + lane] = o;
    }
}

// ---------------- gathered emb A-perm (K2): rows are emb[tok(m)] ----------------
__global__ void permA_emb(const float* __restrict__ emb, const int* __restrict__ captions,
                          uint4* __restrict__ outp) {
    const int K = E_, ktcnt = E_ / 16, kcnt = E_ / 128;   // 16, 2
    int total = (M_ / 16) * ktcnt * 32;
    for (int i = blockIdx.x * blockDim.x + threadIdx.x; i < total; i += gridDim.x * blockDim.x) {
        int lane = i & 31;
        int kt = (i >> 5) % ktcnt;
        int mt = (i >> 5) / ktcnt;
        int g = lane >> 2, q = lane & 3;
        int m0 = mt * 16 + g, m1 = m0 + 8;
        int c0 = kt * 16 + 2 * q;
        int b0 = m0 & 31, t0 = m0 >> 5;
        int b1 = m1 & 31, t1 = m1 >> 5;
        int tok0 = captions[b0 * T_ + (t0 ? t0 - 1 : 0)];
        int tok1 = captions[b1 * T_ + (t1 ? t1 - 1 : 0)];
        const float* p0 = emb + (size_t)tok0 * K + c0;
        const float* p1 = emb + (size_t)tok1 * K + c0;
        float2 v0 = *(const float2*)(p0);
        float2 v1 = *(const float2*)(p1);
        float2 v2 = *(const float2*)(p0 + 8);
        float2 v3 = *(const float2*)(p1 + 8);
        uint4 o;
        o.x = pack2(v0.x, v0.y);
        o.y = pack2(v1.x, v1.y);
        o.z = pack2(v2.x, v2.y);
        o.w = pack2(v3.x, v3.y);
        int mb = mt >> 3, tm = mt & 7, kc = kt >> 3, k16 = kt & 7;
        outp[((((mb * kcnt + kc) * 8 + k16) * 8 + tm) << 5) + lane] = o;
    }
}

// ---------------- generic B-perm: fp32 [N x K] -> fp16 m16n8k16 B-fragments ----------------
__global__ void permB_g(const float* __restrict__ src, uint4* __restrict__ outp,
                        int K, int kcnt, int Npad, int nValid) {
    int ktcnt = K >> 4;
    int total = (Npad >> 4) * ktcnt * 32;
    for (int i = blockIdx.x * blockDim.x + threadIdx.x; i < total; i += gridDim.x * blockDim.x) {
        int lane = i & 31;
        int kt = (i >> 5) % ktcnt;
        int nt2 = (i >> 5) / ktcnt;
        int g = lane >> 2, q = lane & 3;
        int na = nt2 * 16 + g;
        int nb8 = na + 8;
        int c0 = kt * 16 + 2 * q;
        float2 a0 = make_float2(0.f, 0.f), a1 = a0, b0 = a0, b1 = a0;
        if (na < nValid) {
            const float* p = src + (size_t)na * K + c0;
            a0 = *(const float2*)(p);
            a1 = *(const float2*)(p + 8);
        }
        if (nb8 < nValid) {
            const float* p = src + (size_t)nb8 * K + c0;
            b0 = *(const float2*)(p);
            b1 = *(const float2*)(p + 8);
        }
        uint4 o;
        o.x = pack2(a0.x, a0.y);
        o.y = pack2(a1.x, a1.y);
        o.z = pack2(b0.x, b0.y);
        o.w = pack2(b1.x, b1.y);
        int nbk = nt2 >> 4, tn2 = nt2 & 15, kc = kt >> 3, k16 = kt & 7;
        outp[((((nbk * kcnt + kc) * 8 + k16) * 16 + tn2) << 5) + lane] = o;
    }
}

// ---------------- transposed B-perm: B[n,k] = src[k*N0 + n]  (for W1^T) ----------------
__global__ void permBT_g(const float* __restrict__ src, uint4* __restrict__ outp,
                         int K, int kcnt, int N0) {
    int ktcnt = K >> 4;
    int total = (N0 >> 4) * ktcnt * 32;
    for (int i = blockIdx.x * blockDim.x + threadIdx.x; i < total; i += gridDim.x * blockDim.x) {
        int lane = i & 31;
        int kt = (i >> 5) % ktcnt;
        int nt2 = (i >> 5) / ktcnt;
        int g = lane >> 2, q = lane & 3;
        int na = nt2 * 16 + g;
        int c0 = kt * 16 + 2 * q;
        uint4 o;
        o.x = pack2(src[(size_t)c0 * N0 + na],       src[(size_t)(c0 + 1) * N0 + na]);
        o.y = pack2(src[(size_t)(c0 + 8) * N0 + na], src[(size_t)(c0 + 9) * N0 + na]);
        o.z = pack2(src[(size_t)c0 * N0 + na + 8],       src[(size_t)(c0 + 1) * N0 + na + 8]);
        o.w = pack2(src[(size_t)(c0 + 8) * N0 + na + 8], src[(size_t)(c0 + 9) * N0 + na + 8]);
        int nbk = nt2 >> 4, tn2 = nt2 & 15, kc = kt >> 3, k16 = kt & 7;
        outp[((((nbk * kcnt + kc) * 8 + k16) * 16 + tn2) << 5) + lane] = o;
    }
}

// ---------------- shared fp16-mma mainloop (CTA 128x256, BK=128 chunks) ----------------
__device__ __forceinline__ void gemm_mainloop(const uint4* __restrict__ Asrc,
                                              const uint4* __restrict__ Bsrc,
                                              int nkt, char* st,
                                              int tid, int lane, int wm, int wn,
                                              float acc[4][4][4]) {
    uint32_t stb = smem_u32(st);
    auto prefetch = [&](int c) {
        uint32_t d = stb + (c & 1) * ST_BYTES;
        const uint4* a4 = Asrc + (size_t)c * 2048;
        const uint4* b4 = Bsrc + (size_t)c * 4096;
        #pragma unroll
        for (int i = 0; i < 4; i++)
            cp16(d + (tid + i * 512) * 16, a4 + tid + i * 512);
        uint32_t db = d + ST_A_BYTES;
        #pragma unroll
        for (int i = 0; i < 8; i++)
            cp16(db + (tid + i * 512) * 16, b4 + tid + i * 512);
        asm volatile("cp.async.commit_group;\n" ::: "memory");
    };

    #pragma unroll
    for (int mi = 0; mi < 4; mi++)
        #pragma unroll
        for (int ni = 0; ni < 4; ni++)
            #pragma unroll
            for (int r = 0; r < 4; r++) acc[mi][ni][r] = 0.f;

    prefetch(0);
    prefetch(1);

    for (int c = 0; c < nkt; c++) {
        if (c < nkt - 2)
            asm volatile("cp.async.wait_group 1;\n" ::: "memory");
        else
            asm volatile("cp.async.wait_group 0;\n" ::: "memory");
        __syncthreads();

        const uint4* SA = (const uint4*)(st + (c & 1) * ST_BYTES);     // [k16(8)][tm(8)][lane]
        const uint4* SB = SA + 2048;                                    // [k16(8)][tn2(16)][lane]

        #pragma unroll
        for (int k16 = 0; k16 < 8; k16++) {
            uint4 af[4], bf[2];
            #pragma unroll
            for (int mi = 0; mi < 4; mi++)
                af[mi] = SA[((k16 * 8 + wm * 4 + mi) << 5) + lane];
            #pragma unroll
            for (int n2 = 0; n2 < 2; n2++)
                bf[n2] = SB[((k16 * 16 + wn * 2 + n2) << 5) + lane];
            #pragma unroll
            for (int mi = 0; mi < 4; mi++)
                #pragma unroll
                for (int n2 = 0; n2 < 2; n2++) {
                    mma_f16(acc[mi][n2 * 2],     (const uint32_t*)&af[mi], bf[n2].x, bf[n2].y);
                    mma_f16(acc[mi][n2 * 2 + 1], (const uint32_t*)&af[mi], bf[n2].z, bf[n2].w);
                }
        }
        __syncthreads();
        if (c + 2 < nkt) prefetch(c + 2);
    }
}

// ---------------- K2: xg = gathered_emb @ W_ih^T (fp16 mma, fp32 out) ----------------
__global__ __launch_bounds__(512, 1)
void gemm_xg(const uint4* __restrict__ Ap, const uint4* __restrict__ Bp,
             float* __restrict__ xg) {
    extern __shared__ char st[];
    int tid = threadIdx.x, lane = tid & 31, warp = tid >> 5;
    int wm = warp >> 3, wn = warp & 7;
    int mb = blockIdx.x, nb = blockIdx.y;

    float acc[4][4][4];
    gemm_mainloop(Ap + (size_t)mb * 2 * 2048, Bp + (size_t)nb * 2 * 4096, 2,
                  st, tid, lane, wm, wn, acc);

    int g = lane >> 2, q = lane & 3;
    #pragma unroll
    for (int mi = 0; mi < 4; mi++) {
        int mA = mb * 128 + wm * 64 + mi * 16 + g;
        int mB = mA + 8;
        #pragma unroll
        for (int ni = 0; ni < 4; ni++) {
            int cc = wn * 32 + (ni >> 1) * 16 + (ni & 1) * 8 + q * 2;
            int n = nb * BN_ + cc;
            xg[(size_t)mA * G4_ + n]     = acc[mi][ni][0];
            xg[(size_t)mA * G4_ + n + 1] = acc[mi][ni][1];
            xg[(size_t)mB * G4_ + n]     = acc[mi][ni][2];
            xg[(size_t)mB * G4_ + n + 1] = acc[mi][ni][3];
        }
    }
}

// ---------------- Wc GEMM: Wc = W2 @ W1 -> K5' B-fragments (kcnt=4 layout) ----------------
// A = W2 A-frags [VPAD2 x 1024], B = W1^T B-frags [512 x 1024]. grid (394, 2).
__global__ __launch_bounds__(512, 1)
void gemm_wc(const uint4* __restrict__ Ap, const uint4* __restrict__ Bp,
             uint4* __restrict__ outp) {
    extern __shared__ char st[];
    int tid = threadIdx.x, lane = tid & 31, warp = tid >> 5;
    int wm = warp >> 3, wn = warp & 7;
    int mb = blockIdx.x, nb = blockIdx.y;

    float acc[4][4][4];
    gemm_mainloop(Ap + (size_t)mb * 8 * 2048, Bp + (size_t)nb * 8 * 4096, 8,
                  st, tid, lane, wm, wn, acc);

    // epilogue: D[v, h] -> K5' B-frags (n-dim = v, k-dim = h, kcnt = 4)
    #pragma unroll
    for (int mi = 0; mi < 4; mi++) {
        int nt2g = mb * 8 + wm * 4 + mi;       // v n16-tile index
        int nbk = nt2g >> 4, tn2 = nt2g & 15;
        #pragma unroll
        for (int j = 0; j < 2; j++) {
            int kt = nb * 16 + wn * 2 + j;     // h k16-tile index (0..31)
            int kc = kt >> 3, k16 = kt & 7;
            float* L = acc[mi][2 * j];
            float* Hh = acc[mi][2 * j + 1];
            uint4 o;
            o.x = pack2(L[0], L[1]);
            o.y = pack2(Hh[0], Hh[1]);
            o.z = pack2(L[2], L[3]);
            o.w = pack2(Hh[2], Hh[3]);
            outp[((((nbk * 4 + kc) * 8 + k16) * 16 + tn2) << 5) + lane] = o;
        }
    }
}

// ---------------- K5': logits = hs @ Wc^T + b2' ----------------
__global__ __launch_bounds__(512, 1)
void logits_mma(const uint4* __restrict__ Ap, const uint4* __restrict__ Bp,
                const float* __restrict__ b2p, float* __restrict__ out) {
    __shared__ float b2s[BN_];
    extern __shared__ char st[];
    int tid = threadIdx.x, lane = tid & 31, warp = tid >> 5;
    int wm = warp >> 3, wn = warp & 7;
    int mb = blockIdx.x, nb = blockIdx.y;

    if (tid < BN_) { int v = nb * BN_ + tid; b2s[tid] = (v < V_) ? b2p[v] : 0.f; }

    float acc[4][4][4];
    gemm_mainloop(Ap + (size_t)mb * 4 * 2048, Bp + (size_t)nb * 4 * 4096, 4,
                  st, tid, lane, wm, wn, acc);

    // epilogue: m = t*B+b ; out[b][t][v]
    int g = lane >> 2, q = lane & 3;
    #pragma unroll
    for (int mi = 0; mi < 4; mi++) {
        int mA = mb * 128 + wm * 64 + mi * 16 + g;
        int mB = mA + 8;
        size_t offA = ((size_t)(mA & 31) * T_ + (size_t)(mA >> 5)) * (size_t)V_;
        size_t offB = ((size_t)(mB & 31) * T_ + (size_t)(mB >> 5)) * (size_t)V_;
        #pragma unroll
        for (int ni = 0; ni < 4; ni++) {
            int cc = wn * 32 + (ni >> 1) * 16 + (ni & 1) * 8 + q * 2;
            int n = nb * BN_ + cc;
            if (n < V_) {
                out[offA + n] = acc[mi][ni][0] + b2s[cc];
                out[offB + n] = acc[mi][ni][2] + b2s[cc];
                if (n + 1 < V_) {
                    out[offA + n + 1] = acc[mi][ni][1] + b2s[cc + 1];
                    out[offB + n + 1] = acc[mi][ni][3] + b2s[cc + 1];
                }
            }
        }
    }
}

// ---------------- launch ----------------
extern "C" void kernel_launch(void* const* d_in, const int* in_sizes, int n_in,
                              void* d_out, int out_size) {
    const float* features = (const float*)d_in[0];
    const int*   captions = (const int*)d_in[1];
    const float* emb      = (const float*)d_in[2];
    const float* W_ih     = (const float*)d_in[3];
    const float* W_hh     = (const float*)d_in[4];
    const float* b_ih     = (const float*)d_in[5];
    const float* b_hh     = (const float*)d_in[6];
    const float* W1       = (const float*)d_in[7];
    const float* b1       = (const float*)d_in[8];
    const float* W2       = (const float*)d_in[9];
    const float* b2       = (const float*)d_in[10];
    float* out = (float*)d_out;

    void *p_base, *p_xg, *p_hs, *p_b2p, *p_embp, *p_wihp, *p_hsp, *p_w1t, *p_w2a, *p_wcp;
    cudaGetSymbolAddress(&p_base, g_base);
    cudaGetSymbolAddress(&p_xg,   g_xg);
    cudaGetSymbolAddress(&p_hs,   g_hs);
    cudaGetSymbolAddress(&p_b2p,  g_b2p);
    cudaGetSymbolAddress(&p_embp, g_embp);
    cudaGetSymbolAddress(&p_wihp, g_wihp);
    cudaGetSymbolAddress(&p_hsp,  g_hsp);
    cudaGetSymbolAddress(&p_w1t,  g_w1t);
    cudaGetSymbolAddress(&p_w2a,  g_w2a);
    cudaGetSymbolAddress(&p_wcp,  g_wcp);
    float* base = (float*)p_base;
    float* xg   = (float*)p_xg;
    float* hs   = (float*)p_hs;

    cudaFuncSetAttribute(gemm_xg,    cudaFuncAttributeMaxDynamicSharedMemorySize, SMEM_DYN);
    cudaFuncSetAttribute(gemm_wc,    cudaFuncAttributeMaxDynamicSharedMemorySize, SMEM_DYN);
    cudaFuncSetAttribute(logits_mma, cudaFuncAttributeMaxDynamicSharedMemorySize, SMEM_DYN);

    // Streams/events for fork-join capture.
    static cudaStream_t s2 = nullptr, s3 = nullptr;
    static cudaEvent_t evFork = nullptr, evJoin2 = nullptr, ev3a = nullptr, ev3b = nullptr;
    if (s2 == nullptr) {
        cudaStreamCreateWithFlags(&s2, cudaStreamNonBlocking);
        cudaStreamCreateWithFlags(&s3, cudaStreamNonBlocking);
        cudaEventCreateWithFlags(&evFork,  cudaEventDisableTiming);
        cudaEventCreateWithFlags(&evJoin2, cudaEventDisableTiming);
        cudaEventCreateWithFlags(&ev3a,    cudaEventDisableTiming);
        cudaEventCreateWithFlags(&ev3b,    cudaEventDisableTiming);
    }

    // ---- fork ----
    cudaEventRecord(evFork, 0);
    cudaStreamWaitEvent(s2, evFork, 0);
    cudaStreamWaitEvent(s3, evFork, 0);

    // s2: weight-only branch -> Wc = W2 @ W1 in K5' B-frag layout
    permBT_g<<<64, 256, 0, s2>>>(W1, (uint4*)p_w1t, H2_, 8, H_);
    permA_g<<<4096, 256, 0, s2>>>(W2, (uint4*)p_w2a, VPAD2_, H2_, 8, V_);
    {
        dim3 grid(VPAD2_ / 128, 2);   // (394, 2)
        gemm_wc<<<grid, 512, SMEM_DYN, s2>>>((const uint4*)p_w2a, (const uint4*)p_w1t,
                                             (uint4*)p_wcp);
    }
    cudaEventRecord(evJoin2, s2);

    // s3: base gates (for scan), then b2' = b2 + W2@b1 (for K5')
    base_kernel<<<B_, 256, 0, s3>>>(features, W_hh, b_ih, b_hh, base);
    cudaEventRecord(ev3a, s3);
    bias2_kernel<<<(V_ * 32 + 255) / 256, 256, 0, s3>>>(W2, b1, b2, (float*)p_b2p);
    cudaEventRecord(ev3b, s3);

    // ---- main-stream chain ----
    permB_g<<<256, 256>>>(W_ih, (uint4*)p_wihp, E_, 2, G4_, G4_);
    permA_emb<<<256, 256>>>(emb, captions, (uint4*)p_embp);

    // K2: xg = emb_gathered @ W_ih^T  (fp16 mma)
    {
        dim3 grid(M_ / BM_, G4_ / BN_);   // (16, 8)
        gemm_xg<<<grid, 512, SMEM_DYN>>>((const uint4*)p_embp, (const uint4*)p_wihp, xg);
    }

    cudaStreamWaitEvent(0, ev3a, 0);

    // K3: LSTM scan
    lstm_scan<<<128, 128>>>(xg, base, hs);

    // prep: hs A-frags (K=512, kcnt=4) -- consumed directly by K5'
    permA_g<<<256, 256>>>(hs, (uint4*)p_hsp, M_, H_, 4, M_);

    // join: K5' needs Wc (s2) and b2' (s3)
    cudaStreamWaitEvent(0, evJoin2, 0);
    cudaStreamWaitEvent(0, ev3b, 0);

    // K5': logits = hs @ Wc^T + b2'
    {
        dim3 grid(M_ / BM_, VPAD2_ / BN_);   // (16, 197)
        logits_mma<<<grid, 512, SMEM_DYN>>>((const uint4*)p_hsp, (const uint4*)p_wcp,
                                            (const float*)p_b2p, out);
    }
}

// round 17
// speedup vs baseline: 1.4420x; 1.0252x over previous
#include <cuda_runtime.h>
#include <cuda_fp16.h>
#include <cstdint>

// Problem constants
#define B_  32
#define T_  64
#define V_  50257
#define E_  256
#define H_  512
#define G4_ 2048   // 4*H
#define H2_ 1024   // 2*H
#define M_  2048   // T*B
#define VPAD2_ 50432  // 197*256 = 394*128

// mma tiling: CTA 128x256, 512 threads (16 warps 2x8), warp tile 64x32, BK=128
#define BM_ 128
#define BN_ 256
#define ST_A_BYTES 32768          // 128*128*2
#define ST_B_BYTES 65536          // 256*128*2
#define ST_BYTES   98304
#define SMEM_DYN   (2 * ST_BYTES) // 196608
#define NT5_ ((M_ / BM_) * (VPAD2_ / BN_))   // 3152 K5' tiles

// ---------------- scratch (device globals; no allocation allowed) ----------------
__device__ float g_base[B_ * G4_];
__device__ float g_xg[M_ * G4_];
__device__ float g_hs[M_ * H_];
__device__ float g_b2p[VPAD2_];                                     // b2 + W2@b1
__device__ __align__(16) __half g_embp[(size_t)M_ * E_];            // gathered emb A-frags (K2)
__device__ __align__(16) __half g_wihp[(size_t)G4_ * E_];           // W_ih B-frags (K2)
__device__ __align__(16) __half g_hsp[(size_t)M_ * H_];             // hs A-frags (K5')
__device__ __align__(16) __half g_w1t[(size_t)H_ * H2_];            // W1^T B-frags (Wc gemm)
__device__ __align__(16) __half g_w2a[(size_t)VPAD2_ * H2_];        // W2 A-frags (Wc gemm)
__device__ __align__(16) __half g_wcp[(size_t)VPAD2_ * H_];         // Wc B-frags (K5')

// ---------------- helpers ----------------
__device__ __forceinline__ void mma_f16(float* d, const uint32_t* a, uint32_t b0, uint32_t b1) {
    asm volatile(
        "mma.sync.aligned.m16n8k16.row.col.f32.f16.f16.f32 "
        "{%0,%1,%2,%3}, {%4,%5,%6,%7}, {%8,%9}, {%0,%1,%2,%3};\n"
        : "+f"(d[0]), "+f"(d[1]), "+f"(d[2]), "+f"(d[3])
        : "r"(a[0]), "r"(a[1]), "r"(a[2]), "r"(a[3]), "r"(b0), "r"(b1));
}

__device__ __forceinline__ float sigf(float x) {
    return __fdividef(1.f, 1.f + __expf(-x));
}
__device__ __forceinline__ float ftanh(float x) {
    float e = __expf(2.f * x);
    return 1.f - __fdividef(2.f, e + 1.f);
}

__device__ __forceinline__ uint32_t smem_u32(const void* p) {
    return (uint32_t)__cvta_generic_to_shared(p);
}

__device__ __forceinline__ void cp16(uint32_t dst, const void* src) {
    asm volatile("cp.async.cg.shared.global [%0], [%1], 16;\n"
                 :: "r"(dst), "l"(src) : "memory");
}

__device__ __forceinline__ uint32_t pack2(float lo, float hi) {
    __half2 h = __floats2half2_rn(lo, hi);
    return *(uint32_t*)&h;
}

// ---------------- K1: base gates, warp-per-(b,g) ----------------
__global__ void base_kernel(const float* __restrict__ feat,
                            const float* __restrict__ W_hh,
                            const float* __restrict__ b_ih,
                            const float* __restrict__ b_hh,
                            float* __restrict__ base) {
    int w = (blockIdx.x * blockDim.x + threadIdx.x) >> 5;   // 0 .. B_*G4_-1
    int lane = threadIdx.x & 31;
    if (w >= B_ * G4_) return;
    int b = w >> 11, g = w & (G4_ - 1);
    const float4* w4 = (const float4*)(W_hh + (size_t)g * H_);
    const float4* f4 = (const float4*)(feat + (size_t)b * H_);
    float s = 0.f;
    #pragma unroll
    for (int j = 0; j < 4; j++) {
        float4 a = w4[lane + j * 32], f = f4[lane + j * 32];
        s += a.x * f.x + a.y * f.y + a.z * f.z + a.w * f.w;
    }
    #pragma unroll
    for (int o = 16; o; o >>= 1) s += __shfl_xor_sync(0xFFFFFFFFu, s, o);
    if (lane == 0) base[b * G4_ + g] = s + b_ih[g] + b_hh[g];
}

// ---------------- b2' = b2 + W2 @ b1 (warp per row, deterministic) ----------------
__global__ void bias2_kernel(const float* __restrict__ W2, const float* __restrict__ b1,
                             const float* __restrict__ b2, float* __restrict__ b2p) {
    int w = (blockIdx.x * blockDim.x + threadIdx.x) >> 5;
    int lane = threadIdx.x & 31;
    if (w >= V_) return;
    const float4* row = (const float4*)(W2 + (size_t)w * H2_);
    const float4* bb = (const float4*)b1;
    float s = 0.f;
    #pragma unroll
    for (int j = 0; j < 8; j++) {
        float4 a = row[lane + j * 32], c = bb[lane + j * 32];
        s += a.x * c.x + a.y * c.y + a.z * c.z + a.w * c.w;
    }
    #pragma unroll
    for (int o = 16; o; o >>= 1) s += __shfl_xor_sync(0xFFFFFFFFu, s, o);
    if (lane == 0) b2p[w] = s + b2[w];
}

// ---------------- K3: LSTM scan (depth-8 prefetch) ----------------
__global__ void lstm_scan(const float* __restrict__ xg,
                          const float* __restrict__ base,
                          float* __restrict__ hs) {
    int idx = blockIdx.x * blockDim.x + threadIdx.x;
    int b = idx >> 9, h = idx & 511;
    float bi = base[b * G4_ + h];
    float bff = base[b * G4_ + H_ + h];
    float bg = base[b * G4_ + 2 * H_ + h];
    float bo = base[b * G4_ + 3 * H_ + h];

    const float* xr = xg + (size_t)b * G4_ + h;
    const size_t step = (size_t)B_ * G4_;

    float4 pf[8];
    #pragma unroll
    for (int j = 0; j < 8; j++) {
        const float* p = xr + (size_t)j * step;
        pf[j] = make_float4(p[0], p[H_], p[2 * H_], p[3 * H_]);
    }

    float c = 0.f;
    float* hp = hs + (size_t)b * H_ + h;
    #pragma unroll 8
    for (int t = 0; t < T_; t++) {
        float4 cur = pf[t & 7];
        if (t + 8 < T_) {
            const float* p = xr + (size_t)(t + 8) * step;
            pf[t & 7] = make_float4(p[0], p[H_], p[2 * H_], p[3 * H_]);
        }
        float i = sigf(cur.x + bi);
        float f = sigf(cur.y + bff);
        float g = ftanh(cur.z + bg);
        float o = sigf(cur.w + bo);
        c = f * c + i * g;
        hp[(size_t)t * B_ * H_] = o * ftanh(c);
    }
}

// ---------------- generic A-perm: fp32 [M x K] -> fp16 m16n8k16 A-fragments (row-padded) ----------------
__global__ void permA_g(const float* __restrict__ src, uint4* __restrict__ outp,
                        int Mpad, int K, int kcnt, int nValid) {
    int ktcnt = K >> 4;
    int total = (Mpad >> 4) * ktcnt * 32;
    for (int i = blockIdx.x * blockDim.x + threadIdx.x; i < total; i += gridDim.x * blockDim.x) {
        int lane = i & 31;
        int kt = (i >> 5) % ktcnt;
        int mt = (i >> 5) / ktcnt;
        int g = lane >> 2, q = lane & 3;
        int r0 = mt * 16 + g, r1 = r0 + 8;
        int c0 = kt * 16 + 2 * q;
        float2 v0 = make_float2(0.f, 0.f), v1 = v0, v2 = v0, v3 = v0;
        if (r0 < nValid) {
            const float* p0 = src + (size_t)r0 * K + c0;
            v0 = *(const float2*)(p0);
            v2 = *(const float2*)(p0 + 8);
        }
        if (r1 < nValid) {
            const float* p1 = src + (size_t)r1 * K + c0;
            v1 = *(const float2*)(p1);
            v3 = *(const float2*)(p1 + 8);
        }
        uint4 o;
        o.x = pack2(v0.x, v0.y);
        o.y = pack2(v1.x, v1.y);
        o.z = pack2(v2.x, v2.y);
        o.w = pack2(v3.x, v3.y);
        int mb = mt >> 3, tm = mt & 7, kc = kt >> 3, k16 = kt & 7;
        outp[((((mb * kcnt + kc) * 8 + k16) * 8 + tm) << 5) + lane] = o;
    }
}

// ---------------- gathered emb A-perm (K2) ----------------
__global__ void permA_emb(const float* __restrict__ emb, const int* __restrict__ captions,
                          uint4* __restrict__ outp) {
    const int K = E_, ktcnt = E_ / 16, kcnt = E_ / 128;   // 16, 2
    int total = (M_ / 16) * ktcnt * 32;
    for (int i = blockIdx.x * blockDim.x + threadIdx.x; i < total; i += gridDim.x * blockDim.x) {
        int lane = i & 31;
        int kt = (i >> 5) % ktcnt;
        int mt = (i >> 5) / ktcnt;
        int g = lane >> 2, q = lane & 3;
        int m0 = mt * 16 + g, m1 = m0 + 8;
        int c0 = kt * 16 + 2 * q;
        int b0 = m0 & 31, t0 = m0 >> 5;
        int b1 = m1 & 31, t1 = m1 >> 5;
        int tok0 = captions[b0 * T_ + (t0 ? t0 - 1 : 0)];
        int tok1 = captions[b1 * T_ + (t1 ? t1 - 1 : 0)];
        const float* p0 = emb + (size_t)tok0 * K + c0;
        const float* p1 = emb + (size_t)tok1 * K + c0;
        float2 v0 = *(const float2*)(p0);
        float2 v1 = *(const float2*)(p1);
        float2 v2 = *(const float2*)(p0 + 8);
        float2 v3 = *(const float2*)(p1 + 8);
        uint4 o;
        o.x = pack2(v0.x, v0.y);
        o.y = pack2(v1.x, v1.y);
        o.z = pack2(v2.x, v2.y);
        o.w = pack2(v3.x, v3.y);
        int mb = mt >> 3, tm = mt & 7, kc = kt >> 3, k16 = kt & 7;
        outp[((((mb * kcnt + kc) * 8 + k16) * 8 + tm) << 5) + lane] = o;
    }
}

// ---------------- generic B-perm: fp32 [N x K] -> fp16 m16n8k16 B-fragments ----------------
__global__ void permB_g(const float* __restrict__ src, uint4* __restrict__ outp,
                        int K, int kcnt, int Npad, int nValid) {
    int ktcnt = K >> 4;
    int total = (Npad >> 4) * ktcnt * 32;
    for (int i = blockIdx.x * blockDim.x + threadIdx.x; i < total; i += gridDim.x * blockDim.x) {
        int lane = i & 31;
        int kt = (i >> 5) % ktcnt;
        int nt2 = (i >> 5) / ktcnt;
        int g = lane >> 2, q = lane & 3;
        int na = nt2 * 16 + g;
        int nb8 = na + 8;
        int c0 = kt * 16 + 2 * q;
        float2 a0 = make_float2(0.f, 0.f), a1 = a0, b0 = a0, b1 = a0;
        if (na < nValid) {
            const float* p = src + (size_t)na * K + c0;
            a0 = *(const float2*)(p);
            a1 = *(const float2*)(p + 8);
        }
        if (nb8 < nValid) {
            const float* p = src + (size_t)nb8 * K + c0;
            b0 = *(const float2*)(p);
            b1 = *(const float2*)(p + 8);
        }
        uint4 o;
        o.x = pack2(a0.x, a0.y);
        o.y = pack2(a1.x, a1.y);
        o.z = pack2(b0.x, b0.y);
        o.w = pack2(b1.x, b1.y);
        int nbk = nt2 >> 4, tn2 = nt2 & 15, kc = kt >> 3, k16 = kt & 7;
        outp[((((nbk * kcnt + kc) * 8 + k16) * 16 + tn2) << 5) + lane] = o;
    }
}

// ---------------- transposed B-perm: B[n,k] = src[k*N0 + n]  (for W1^T) ----------------
__global__ void permBT_g(const float* __restrict__ src, uint4* __restrict__ outp,
                         int K, int kcnt, int N0) {
    int ktcnt = K >> 4;
    int total = (N0 >> 4) * ktcnt * 32;
    for (int i = blockIdx.x * blockDim.x + threadIdx.x; i < total; i += gridDim.x * blockDim.x) {
        int lane = i & 31;
        int kt = (i >> 5) % ktcnt;
        int nt2 = (i >> 5) / ktcnt;
        int g = lane >> 2, q = lane & 3;
        int na = nt2 * 16 + g;
        int c0 = kt * 16 + 2 * q;
        uint4 o;
        o.x = pack2(src[(size_t)c0 * N0 + na],       src[(size_t)(c0 + 1) * N0 + na]);
        o.y = pack2(src[(size_t)(c0 + 8) * N0 + na], src[(size_t)(c0 + 9) * N0 + na]);
        o.z = pack2(src[(size_t)c0 * N0 + na + 8],       src[(size_t)(c0 + 1) * N0 + na + 8]);
        o.w = pack2(src[(size_t)(c0 + 8) * N0 + na + 8], src[(size_t)(c0 + 9) * N0 + na + 8]);
        int nbk = nt2 >> 4, tn2 = nt2 & 15, kc = kt >> 3, k16 = kt & 7;
        outp[((((nbk * kcnt + kc) * 8 + k16) * 16 + tn2) << 5) + lane] = o;
    }
}

// ---------------- shared fp16-mma mainloop (CTA 128x256, BK=128 chunks) ----------------
__device__ __forceinline__ void gemm_mainloop(const uint4* __restrict__ Asrc,
                                              const uint4* __restrict__ Bsrc,
                                              int nkt, char* st,
                                              int tid, int lane, int wm, int wn,
                                              float acc[4][4][4]) {
    uint32_t stb = smem_u32(st);
    auto prefetch = [&](int c) {
        uint32_t d = stb + (c & 1) * ST_BYTES;
        const uint4* a4 = Asrc + (size_t)c * 2048;
        const uint4* b4 = Bsrc + (size_t)c * 4096;
        #pragma unroll
        for (int i = 0; i < 4; i++)
            cp16(d + (tid + i * 512) * 16, a4 + tid + i * 512);
        uint32_t db = d + ST_A_BYTES;
        #pragma unroll
        for (int i = 0; i < 8; i++)
            cp16(db + (tid + i * 512) * 16, b4 + tid + i * 512);
        asm volatile("cp.async.commit_group;\n" ::: "memory");
    };

    #pragma unroll
    for (int mi = 0; mi < 4; mi++)
        #pragma unroll
        for (int ni = 0; ni < 4; ni++)
            #pragma unroll
            for (int r = 0; r < 4; r++) acc[mi][ni][r] = 0.f;

    prefetch(0);
    prefetch(1);

    for (int c = 0; c < nkt; c++) {
        if (c < nkt - 2)
            asm volatile("cp.async.wait_group 1;\n" ::: "memory");
        else
            asm volatile("cp.async.wait_group 0;\n" ::: "memory");
        __syncthreads();

        const uint4* SA = (const uint4*)(st + (c & 1) * ST_BYTES);     // [k16(8)][tm(8)][lane]
        const uint4* SB = SA + 2048;                                    // [k16(8)][tn2(16)][lane]

        #pragma unroll
        for (int k16 = 0; k16 < 8; k16++) {
            uint4 af[4], bf[2];
            #pragma unroll
            for (int mi = 0; mi < 4; mi++)
                af[mi] = SA[((k16 * 8 + wm * 4 + mi) << 5) + lane];
            #pragma unroll
            for (int n2 = 0; n2 < 2; n2++)
                bf[n2] = SB[((k16 * 16 + wn * 2 + n2) << 5) + lane];
            #pragma unroll
            for (int mi = 0; mi < 4; mi++)
                #pragma unroll
                for (int n2 = 0; n2 < 2; n2++) {
                    mma_f16(acc[mi][n2 * 2],     (const uint32_t*)&af[mi], bf[n2].x, bf[n2].y);
                    mma_f16(acc[mi][n2 * 2 + 1], (const uint32_t*)&af[mi], bf[n2].z, bf[n2].w);
                }
        }
        __syncthreads();
        if (c + 2 < nkt) prefetch(c + 2);
    }
}

// ---------------- K2: xg = gathered_emb @ W_ih^T (fp16 mma, fp32 out) ----------------
__global__ __launch_bounds__(512, 1)
void gemm_xg(const uint4* __restrict__ Ap, const uint4* __restrict__ Bp,
             float* __restrict__ xg) {
    extern __shared__ char st[];
    int tid = threadIdx.x, lane = tid & 31, warp = tid >> 5;
    int wm = warp >> 3, wn = warp & 7;
    int mb = blockIdx.x, nb = blockIdx.y;

    float acc[4][4][4];
    gemm_mainloop(Ap + (size_t)mb * 2 * 2048, Bp + (size_t)nb * 2 * 4096, 2,
                  st, tid, lane, wm, wn, acc);

    int g = lane >> 2, q = lane & 3;
    #pragma unroll
    for (int mi = 0; mi < 4; mi++) {
        int mA = mb * 128 + wm * 64 + mi * 16 + g;
        int mB = mA + 8;
        #pragma unroll
        for (int ni = 0; ni < 4; ni++) {
            int cc = wn * 32 + (ni >> 1) * 16 + (ni & 1) * 8 + q * 2;
            int n = nb * BN_ + cc;
            xg[(size_t)mA * G4_ + n]     = acc[mi][ni][0];
            xg[(size_t)mA * G4_ + n + 1] = acc[mi][ni][1];
            xg[(size_t)mB * G4_ + n]     = acc[mi][ni][2];
            xg[(size_t)mB * G4_ + n + 1] = acc[mi][ni][3];
        }
    }
}

// ---------------- Wc GEMM (chunked): Wc = W2 @ W1 -> K5' B-fragments ----------------
__global__ __launch_bounds__(512, 1)
void gemm_wc(const uint4* __restrict__ Ap, const uint4* __restrict__ Bp,
             uint4* __restrict__ outp, int mbBase) {
    extern __shared__ char st[];
    int tid = threadIdx.x, lane = tid & 31, warp = tid >> 5;
    int wm = warp >> 3, wn = warp & 7;
    int mb = blockIdx.x, nb = blockIdx.y;

    float acc[4][4][4];
    gemm_mainloop(Ap + (size_t)mb * 8 * 2048, Bp + (size_t)nb * 8 * 4096, 8,
                  st, tid, lane, wm, wn, acc);

    // epilogue: D[v, h] -> K5' B-frags (n-dim = v, k-dim = h, kcnt = 4)
    #pragma unroll
    for (int mi = 0; mi < 4; mi++) {
        int nt2g = (mbBase + mb) * 8 + wm * 4 + mi;   // v n16-tile index (global)
        int nbk = nt2g >> 4, tn2 = nt2g & 15;
        #pragma unroll
        for (int j = 0; j < 2; j++) {
            int kt = nb * 16 + wn * 2 + j;            // h k16-tile index (0..31)
            int kc = kt >> 3, k16 = kt & 7;
            float* L = acc[mi][2 * j];
            float* Hh = acc[mi][2 * j + 1];
            uint4 o;
            o.x = pack2(L[0], L[1]);
            o.y = pack2(Hh[0], Hh[1]);
            o.z = pack2(L[2], L[3]);
            o.w = pack2(Hh[2], Hh[3]);
            outp[((((nbk * 4 + kc) * 8 + k16) * 16 + tn2) << 5) + lane] = o;
        }
    }
}

// ---------------- K5': persistent logits = hs @ Wc^T + b2' ----------------
// grid = nsm. Nested tile loop; next tile's chunks issued before the epilogue.
__global__ __launch_bounds__(512, 1)
void logits_persist(const uint4* __restrict__ Ap, const uint4* __restrict__ Bp,
                    const float* __restrict__ b2p, float* __restrict__ out) {
    __shared__ float b2s[BN_];
    extern __shared__ char st[];
    uint32_t stb = smem_u32(st);
    int tid = threadIdx.x, lane = tid & 31, warp = tid >> 5;
    int wm = warp >> 3, wn = warp & 7;
    int bid = blockIdx.x, G = gridDim.x;

    int ntile = (NT5_ - bid + G - 1) / G;
    int total = ntile * 4;

    auto prefetch = [&](int pos) {
        int t2 = bid + (pos >> 2) * G;
        int c = pos & 3, mb2 = t2 & 15, nb2 = t2 >> 4;
        uint32_t d = stb + (pos & 1) * ST_BYTES;
        const uint4* a4 = Ap + (size_t)(mb2 * 4 + c) * 2048;
        const uint4* b4 = Bp + (size_t)(nb2 * 4 + c) * 4096;
        #pragma unroll
        for (int i = 0; i < 4; i++)
            cp16(d + (tid + i * 512) * 16, a4 + tid + i * 512);
        uint32_t db = d + ST_A_BYTES;
        #pragma unroll
        for (int i = 0; i < 8; i++)
            cp16(db + (tid + i * 512) * 16, b4 + tid + i * 512);
        asm volatile("cp.async.commit_group;\n" ::: "memory");
    };

    float acc[4][4][4];
    #pragma unroll
    for (int mi = 0; mi < 4; mi++)
        #pragma unroll
        for (int ni = 0; ni < 4; ni++)
            #pragma unroll
            for (int r = 0; r < 4; r++) acc[mi][ni][r] = 0.f;

    prefetch(0);
    prefetch(1);

    int g = lane >> 2, q = lane & 3;

    for (int i = 0; i < ntile; i++) {
        int t = bid + i * G;
        int mb = t & 15, nb = t >> 4;

        // stage bias for this tile (b2s reuse protected by end-of-tile sync)
        if (tid < BN_) { int v = nb * BN_ + tid; b2s[tid] = (v < V_) ? b2p[v] : 0.f; }

        #pragma unroll
        for (int c = 0; c < 4; c++) {
            int pos = i * 4 + c;
            if (pos < total - 1)
                asm volatile("cp.async.wait_group 1;\n" ::: "memory");
            else
                asm volatile("cp.async.wait_group 0;\n" ::: "memory");
            __syncthreads();

            const uint4* SA = (const uint4*)(st + (pos & 1) * ST_BYTES);
            const uint4* SB = SA + 2048;

            #pragma unroll
            for (int k16 = 0; k16 < 8; k16++) {
                uint4 af[4], bf[2];
                #pragma unroll
                for (int mi = 0; mi < 4; mi++)
                    af[mi] = SA[((k16 * 8 + wm * 4 + mi) << 5) + lane];
                #pragma unroll
                for (int n2 = 0; n2 < 2; n2++)
                    bf[n2] = SB[((k16 * 16 + wn * 2 + n2) << 5) + lane];
                #pragma unroll
                for (int mi = 0; mi < 4; mi++)
                    #pragma unroll
                    for (int n2 = 0; n2 < 2; n2++) {
                        mma_f16(acc[mi][n2 * 2],     (const uint32_t*)&af[mi], bf[n2].x, bf[n2].y);
                        mma_f16(acc[mi][n2 * 2 + 1], (const uint32_t*)&af[mi], bf[n2].z, bf[n2].w);
                    }
            }
            __syncthreads();
            if (pos + 2 < total) prefetch(pos + 2);   // next tile's loads fly during epilogue
        }

        // epilogue: m = t*B+b ; out[b][t][v]
        #pragma unroll
        for (int mi = 0; mi < 4; mi++) {
            int mA = mb * 128 + wm * 64 + mi * 16 + g;
            int mB = mA + 8;
            size_t offA = ((size_t)(mA & 31) * T_ + (size_t)(mA >> 5)) * (size_t)V_;
            size_t offB = ((size_t)(mB & 31) * T_ + (size_t)(mB >> 5)) * (size_t)V_;
            #pragma unroll
            for (int ni = 0; ni < 4; ni++) {
                int cc = wn * 32 + (ni >> 1) * 16 + (ni & 1) * 8 + q * 2;
                int n = nb * BN_ + cc;
                if (n < V_) {
                    out[offA + n] = acc[mi][ni][0] + b2s[cc];
                    out[offB + n] = acc[mi][ni][2] + b2s[cc];
                    if (n + 1 < V_) {
                        out[offA + n + 1] = acc[mi][ni][1] + b2s[cc + 1];
                        out[offB + n + 1] = acc[mi][ni][3] + b2s[cc + 1];
                    }
                }
                #pragma unroll
                for (int r = 0; r < 4; r++) acc[mi][ni][r] = 0.f;
            }
        }
        __syncthreads();   // protect b2s before next tile's staging
    }
}

// ---------------- launch ----------------
extern "C" void kernel_launch(void* const* d_in, const int* in_sizes, int n_in,
                              void* d_out, int out_size) {
    const float* features = (const float*)d_in[0];
    const int*   captions = (const int*)d_in[1];
    const float* emb      = (const float*)d_in[2];
    const float* W_ih     = (const float*)d_in[3];
    const float* W_hh     = (const float*)d_in[4];
    const float* b_ih     = (const float*)d_in[5];
    const float* b_hh     = (const float*)d_in[6];
    const float* W1       = (const float*)d_in[7];
    const float* b1       = (const float*)d_in[8];
    const float* W2       = (const float*)d_in[9];
    const float* b2       = (const float*)d_in[10];
    float* out = (float*)d_out;

    void *p_base, *p_xg, *p_hs, *p_b2p, *p_embp, *p_wihp, *p_hsp, *p_w1t, *p_w2a, *p_wcp;
    cudaGetSymbolAddress(&p_base, g_base);
    cudaGetSymbolAddress(&p_xg,   g_xg);
    cudaGetSymbolAddress(&p_hs,   g_hs);
    cudaGetSymbolAddress(&p_b2p,  g_b2p);
    cudaGetSymbolAddress(&p_embp, g_embp);
    cudaGetSymbolAddress(&p_wihp, g_wihp);
    cudaGetSymbolAddress(&p_hsp,  g_hsp);
    cudaGetSymbolAddress(&p_w1t,  g_w1t);
    cudaGetSymbolAddress(&p_w2a,  g_w2a);
    cudaGetSymbolAddress(&p_wcp,  g_wcp);
    float* base = (float*)p_base;
    float* xg   = (float*)p_xg;
    float* hs   = (float*)p_hs;

    cudaFuncSetAttribute(gemm_xg,        cudaFuncAttributeMaxDynamicSharedMemorySize, SMEM_DYN);
    cudaFuncSetAttribute(gemm_wc,        cudaFuncAttributeMaxDynamicSharedMemorySize, SMEM_DYN);
    cudaFuncSetAttribute(logits_persist, cudaFuncAttributeMaxDynamicSharedMemorySize, SMEM_DYN);

    // Streams/events for fork-join capture; SM count for persistent grid.
    static cudaStream_t s2 = nullptr, s3 = nullptr, s4 = nullptr;
    static cudaEvent_t evFork = nullptr, evJoin2 = nullptr, ev3a = nullptr, ev3b = nullptr;
    static cudaEvent_t eC[4] = {nullptr, nullptr, nullptr, nullptr};
    static int nsm = 0;
    if (s2 == nullptr) {
        cudaStreamCreateWithFlags(&s2, cudaStreamNonBlocking);
        cudaStreamCreateWithFlags(&s3, cudaStreamNonBlocking);
        cudaStreamCreateWithFlags(&s4, cudaStreamNonBlocking);
        cudaEventCreateWithFlags(&evFork,  cudaEventDisableTiming);
        cudaEventCreateWithFlags(&evJoin2, cudaEventDisableTiming);
        cudaEventCreateWithFlags(&ev3a,    cudaEventDisableTiming);
        cudaEventCreateWithFlags(&ev3b,    cudaEventDisableTiming);
        for (int i = 0; i < 4; i++) cudaEventCreateWithFlags(&eC[i], cudaEventDisableTiming);
        int dev = 0;
        cudaGetDevice(&dev);
        cudaDeviceGetAttribute(&nsm, cudaDevAttrMultiProcessorCount, dev);
        if (nsm <= 0) nsm = 148;
    }

    // ---- fork ----
    cudaEventRecord(evFork, 0);
    cudaStreamWaitEvent(s2, evFork, 0);
    cudaStreamWaitEvent(s3, evFork, 0);
    cudaStreamWaitEvent(s4, evFork, 0);

    // s4: W2 A-frag perms in 4 v-chunks (mb chunks of 100,100,100,94)
    // s2: W1^T B-frags, then gemm_wc chunk i as soon as perm chunk i lands.
    permBT_g<<<64, 256, 0, s2>>>(W1, (uint4*)p_w1t, H2_, 8, H_);
    {
        const int mbCh[4] = {100, 100, 100, 94};
        int mbBase = 0;
        for (int c = 0; c < 4; c++) {
            int rows = mbCh[c] * 128;
            int rowBase = mbBase * 128;
            int nv = V_ - rowBase;
            if (nv < 0) nv = 0;
            if (nv > rows) nv = rows;
            permA_g<<<1024, 256, 0, s4>>>(W2 + (size_t)rowBase * H2_,
                                          (uint4*)p_w2a + (size_t)mbBase * 16384,
                                          rows, H2_, 8, nv);
            cudaEventRecord(eC[c], s4);
            cudaStreamWaitEvent(s2, eC[c], 0);
            dim3 grid(mbCh[c], 2);
            gemm_wc<<<grid, 512, SMEM_DYN, s2>>>(
                (const uint4*)p_w2a + (size_t)mbBase * 16384,
                (const uint4*)p_w1t, (uint4*)p_wcp, mbBase);
            mbBase += mbCh[c];
        }
    }
    cudaEventRecord(evJoin2, s2);

    // s3: base gates (warp-per-(b,g)), then b2' = b2 + W2@b1
    base_kernel<<<(B_ * G4_ * 32 + 255) / 256, 256, 0, s3>>>(features, W_hh, b_ih, b_hh, base);
    cudaEventRecord(ev3a, s3);
    bias2_kernel<<<(V_ * 32 + 255) / 256, 256, 0, s3>>>(W2, b1, b2, (float*)p_b2p);
    cudaEventRecord(ev3b, s3);

    // ---- main-stream chain ----
    permB_g<<<256, 256>>>(W_ih, (uint4*)p_wihp, E_, 2, G4_, G4_);
    permA_emb<<<256, 256>>>(emb, captions, (uint4*)p_embp);

    // K2: xg = emb_gathered @ W_ih^T  (fp16 mma)
    {
        dim3 grid(M_ / BM_, G4_ / BN_);   // (16, 8)
        gemm_xg<<<grid, 512, SMEM_DYN>>>((const uint4*)p_embp, (const uint4*)p_wihp, xg);
    }

    cudaStreamWaitEvent(0, ev3a, 0);

    // K3: LSTM scan
    lstm_scan<<<128, 128>>>(xg, base, hs);

    // prep: hs A-frags (K=512, kcnt=4) -- consumed directly by K5'
    permA_g<<<256, 256>>>(hs, (uint4*)p_hsp, M_, H_, 4, M_);

    // join: K5' needs Wc (s2) and b2' (s3)
    cudaStreamWaitEvent(0, evJoin2, 0);
    cudaStreamWaitEvent(0, ev3b, 0);

    // K5': persistent logits = hs @ Wc^T + b2'
    {
        int grid = nsm < NT5_ ? nsm : NT5_;
        logits_persist<<<grid, 512, SMEM_DYN>>>((const uint4*)p_hsp, (const uint4*)p_wcp,
                                                (const float*)p_b2p, out);
    }
}